// round 14
// baseline (speedup 1.0000x reference)
#include <cuda_runtime.h>
#include <cuda_fp16.h>
#include <math.h>
#include <stdint.h>

// ---------------- problem constants ----------------
#define TOK   50176
#define CH    512
#define C3    1536
#define FF    2048
#define NHD   16
#define HD    32
#define NWIN  1024

// ---------------- device scratch ----------------
__device__ __half g_wqkv[C3 * CH];            // effective weights, [N][K] K-major
__device__ __half g_wproj[CH * CH];
__device__ __half g_wfc1[FF * CH];
__device__ __half g_wfc2[CH * FF];
__device__ __half g_xw  [(size_t)TOK * CH];
__device__ __half g_qkv [(size_t)TOK * C3];
__device__ __half g_attn[(size_t)TOK * CH];
__device__ float  g_x2  [(size_t)TOK * CH];
__device__ __half g_xn2 [(size_t)TOK * CH];
__device__ __half g_hbuf[(size_t)TOK * FF];
__device__ float  g_bias[16 * 16 * 49 * 52]; // combined rel-pos bias + shift mask

// ---------------- helpers ----------------
__device__ __forceinline__ float gelu_exact(float x) {
    return 0.5f * x * (1.0f + erff(x * 0.70710678118654752f));
}
__device__ __forceinline__ void cp16(uint32_t saddr, const void* g) {
    asm volatile("cp.async.cg.shared.global [%0], [%1], 16;" :: "r"(saddr), "l"(g));
}
__device__ __forceinline__ void cp_commit() { asm volatile("cp.async.commit_group;"); }
__device__ __forceinline__ void cp_wait1()  { asm volatile("cp.async.wait_group 1;"); }

__device__ __forceinline__ void mma16816(float c[4],
        uint32_t a0, uint32_t a1, uint32_t a2, uint32_t a3,
        uint32_t b0, uint32_t b1) {
    asm volatile("mma.sync.aligned.m16n8k16.row.col.f32.f16.f16.f32 "
        "{%0,%1,%2,%3}, {%4,%5,%6,%7}, {%8,%9}, {%0,%1,%2,%3};"
        : "+f"(c[0]), "+f"(c[1]), "+f"(c[2]), "+f"(c[3])
        : "r"(a0), "r"(a1), "r"(a2), "r"(a3), "r"(b0), "r"(b1));
}
__device__ __forceinline__ void ldsm4(uint32_t* r, uint32_t addr) {
    asm volatile("ldmatrix.sync.aligned.m8n8.x4.shared.b16 {%0,%1,%2,%3}, [%4];"
        : "=r"(r[0]), "=r"(r[1]), "=r"(r[2]), "=r"(r[3]) : "r"(addr));
}
__device__ __forceinline__ uint32_t packh2(float a, float b) {
    __half2 h = __floats2half2_rn(a, b);
    return *(uint32_t*)&h;
}

// ---------------- merged preprocessing: LoRA weight folding + bias table ----------------
// blocks 0..12287: weight fusion segments (qkv 3072 | proj 1024 | fc1 4096 | fc2 4096)
// blocks 12288..12543: combined rel-pos bias + shift mask table
__global__ void fuse_all_kernel(
        const float* __restrict__ W0, const float* __restrict__ la0, const float* __restrict__ lb0, __half* __restrict__ o0,
        const float* __restrict__ W1, const float* __restrict__ la1, const float* __restrict__ lb1, __half* __restrict__ o1,
        const float* __restrict__ W2, const float* __restrict__ la2, const float* __restrict__ lb2, __half* __restrict__ o2,
        const float* __restrict__ W3, const float* __restrict__ la3, const float* __restrict__ lb3, __half* __restrict__ o3,
        const float* __restrict__ rpb) {
    int b = blockIdx.x;
    if (b >= 12288) {
        int u = b - 12288;
        int wl = u >> 4, hh = u & 15;
        int wh = wl >> 2, ww = wl & 3;
        float* dst = g_bias + ((size_t)(wl * 16 + hh)) * 49 * 52;
        for (int idx = threadIdx.x; idx < 49 * 52; idx += 256) {
            int n = idx / 52, m = idx - (idx / 52) * 52;
            float v = 0.f;
            if (m < 49) {
                int i1 = n / 7, j1 = n - i1 * 7;
                int i2 = m / 7, j2 = m - i2 * 7;
                v = rpb[((i1 - i2 + 6) * 13 + (j1 - j2 + 6)) * NHD + hh];
                int hs1 = wh * 7 + i1, ws1 = ww * 7 + j1;
                int hs2 = wh * 7 + i2, ws2 = ww * 7 + j2;
                int r1 = (hs1 < 21 ? 0 : (hs1 < 25 ? 1 : 2)) * 3 + (ws1 < 21 ? 0 : (ws1 < 25 ? 1 : 2));
                int r2 = (hs2 < 21 ? 0 : (hs2 < 25 ? 1 : 2)) * 3 + (ws2 < 21 ? 0 : (ws2 < 25 ? 1 : 2));
                if (r1 != r2) v -= 100.f;
            }
            dst[idx] = v;
        }
        return;
    }
    const float *W, *la, *lb; __half* o; int K, base;
    if (b < 3072)      { W = W0; la = la0; lb = lb0; o = o0; K = CH; base = 0; }
    else if (b < 4096) { W = W1; la = la1; lb = lb1; o = o1; K = CH; base = 3072; }
    else if (b < 8192) { W = W2; la = la2; lb = lb2; o = o2; K = CH; base = 4096; }
    else               { W = W3; la = la3; lb = lb3; o = o3; K = FF; base = 8192; }
    int idx = (b - base) * 256 + threadIdx.x;
    int n = idx / K, k = idx - n * K;
    float acc = W[idx];
#pragma unroll
    for (int r = 0; r < 16; r++) acc += lb[n * 16 + r] * la[(size_t)r * K + k];
    o[idx] = __float2half(acc);
}

// ---------------- layernorm, warp-per-row (no barriers, no smem) ----------------
template <bool GATHER>
__global__ __launch_bounds__(256) void ln_kernel(const float* __restrict__ x,
                          const float* __restrict__ s, const float* __restrict__ b,
                          __half* __restrict__ out) {
    int warp = threadIdx.x >> 5, lane = threadIdx.x & 31;
    int t = blockIdx.x * 8 + warp;
    const float* row;
    if (GATHER) {
        int wnd = t / 49, n = t - wnd * 49;
        int bb = wnd >> 4, wl = wnd & 15;
        int wh = wl >> 2, ww = wl & 3;
        int i = n / 7, j = n - i * 7;
        int h = wh * 7 + i + 3; if (h >= 28) h -= 28;
        int wc = ww * 7 + j + 3; if (wc >= 28) wc -= 28;
        row = x + ((size_t)bb * 784 + h * 28 + wc) * CH;
    } else {
        row = x + (size_t)t * CH;
    }
    float4 v[4];
    float sum = 0.f, sq = 0.f;
#pragma unroll
    for (int i = 0; i < 4; i++) {
        v[i] = ((const float4*)row)[lane + 32 * i];
        sum += v[i].x + v[i].y + v[i].z + v[i].w;
        sq  += v[i].x * v[i].x + v[i].y * v[i].y + v[i].z * v[i].z + v[i].w * v[i].w;
    }
#pragma unroll
    for (int o = 16; o > 0; o >>= 1) {
        sum += __shfl_xor_sync(0xffffffffu, sum, o);
        sq  += __shfl_xor_sync(0xffffffffu, sq, o);
    }
    float mean = sum * (1.f / CH);
    float var  = sq * (1.f / CH) - mean * mean;
    float rstd = rsqrtf(var + 1e-5f);
    __half* orow = out + (size_t)t * CH;
#pragma unroll
    for (int i = 0; i < 4; i++) {
        float4 sv = ((const float4*)s)[lane + 32 * i];
        float4 bv = ((const float4*)b)[lane + 32 * i];
        __half2 h0 = __floats2half2_rn((v[i].x - mean) * rstd * sv.x + bv.x,
                                       (v[i].y - mean) * rstd * sv.y + bv.y);
        __half2 h1 = __floats2half2_rn((v[i].z - mean) * rstd * sv.z + bv.z,
                                       (v[i].w - mean) * rstd * sv.w + bv.w);
        uint2 o2; o2.x = *(uint32_t*)&h0; o2.y = *(uint32_t*)&h1;
        ((uint2*)orow)[lane + 32 * i] = o2;
    }
}

// ---------------- windowed attention: 2 heads per block, register-resident P ----------------
// 256 threads: warps 0-3 -> head 2*hp, warps 4-7 -> head 2*hp+1
__global__ __launch_bounds__(256) void attn_kernel() {
    __shared__ __half Qs[2][64][40];   // rows 49..63 zeroed
    __shared__ __half Ks[2][56][40];   // rows 49..55 garbage ok (masked)
    __shared__ __half Vt[2][32][72];   // [d][m]; cols 49..63 zeroed
    int w = blockIdx.x, hp = blockIdx.y;
    int tid = threadIdx.x;
    int lane = tid & 31, warp = tid >> 5;
    int h = warp >> 2, lw = warp & 3;
    int gid = lane >> 2, tig = lane & 3;
    int head = hp * 2 + h;
    const float* Bc = g_bias + ((size_t)((w & 15) * 16 + head)) * 49 * 52;

    // ---- load q/k/v for both heads (128B contiguous per row) + zero pads ----
    size_t base = (size_t)w * 49 * C3 + (size_t)hp * 64;
    for (int idx = tid; idx < 49 * 8; idx += 256) {
        int n = idx >> 3, part = idx & 7;
        int hs = part >> 2, dq = (part & 3) * 8;
        size_t off = base + (size_t)n * C3 + hs * 32 + dq;
        uint4 q4 = *(const uint4*)&g_qkv[off];
        uint4 k4 = *(const uint4*)&g_qkv[off + 512];
        uint4 v4 = *(const uint4*)&g_qkv[off + 1024];
        *(uint4*)&Qs[hs][n][dq] = q4;
        *(uint4*)&Ks[hs][n][dq] = k4;
        uint32_t vp[4] = {v4.x, v4.y, v4.z, v4.w};
#pragma unroll
        for (int p = 0; p < 4; p++) {
            __half2 h2 = *(__half2*)&vp[p];
            Vt[hs][dq + p * 2 + 0][n] = __low2half(h2);
            Vt[hs][dq + p * 2 + 1][n] = __high2half(h2);
        }
    }
    for (int i = tid; i < 2 * 15 * 40; i += 256) {        // Qs rows 49..63 = 0
        int hs = i / (15 * 40), r = i % (15 * 40);
        Qs[hs][49 + r / 40][r % 40] = __float2half(0.f);
    }
    for (int i = tid; i < 2 * 32 * 15; i += 256) {        // Vt cols 49..63 = 0
        int hs = i / (32 * 15), r = i % (32 * 15);
        Vt[hs][r / 15][49 + r % 15] = __float2half(0.f);
    }
    __syncthreads();

    // ---- S = Q*K^T ----
    float c[7][4];
#pragma unroll
    for (int nt = 0; nt < 7; nt++)
#pragma unroll
        for (int i = 0; i < 4; i++) c[nt][i] = 0.f;
    int r0 = lw * 16 + gid;
    int r1 = r0 + 8;
#pragma unroll
    for (int kk = 0; kk < 2; kk++) {
        int col = kk * 16 + tig * 2;
        uint32_t a0 = *(uint32_t*)&Qs[h][r0][col];
        uint32_t a1 = *(uint32_t*)&Qs[h][r1][col];
        uint32_t a2 = *(uint32_t*)&Qs[h][r0][col + 8];
        uint32_t a3 = *(uint32_t*)&Qs[h][r1][col + 8];
#pragma unroll
        for (int nt = 0; nt < 7; nt++) {
            uint32_t b0 = *(uint32_t*)&Ks[h][nt * 8 + gid][col];
            uint32_t b1 = *(uint32_t*)&Ks[h][nt * 8 + gid][col + 8];
            mma16816(c[nt], a0, a1, a2, a3, b0, b1);
        }
    }

    // ---- scale + bias + mask ----
    const float scale = 0.1767766952966369f;
    bool rv0 = r0 < 49, rv1 = r1 < 49;
#pragma unroll
    for (int nt = 0; nt < 7; nt++) {
        int cc = nt * 8 + 2 * tig;
#pragma unroll
        for (int e = 0; e < 2; e++) {
            int col = cc + e;
            bool cv = col < 49;
            c[nt][e]     = (rv0 && cv) ? c[nt][e]     * scale + Bc[r0 * 52 + col] : -1e30f;
            c[nt][2 + e] = (rv1 && cv) ? c[nt][2 + e] * scale + Bc[r1 * 52 + col] : -1e30f;
        }
    }

    // ---- softmax: quad shuffle reduction ----
    {
        float mx0 = -1e30f, mx1 = -1e30f;
#pragma unroll
        for (int nt = 0; nt < 7; nt++) {
            mx0 = fmaxf(mx0, fmaxf(c[nt][0], c[nt][1]));
            mx1 = fmaxf(mx1, fmaxf(c[nt][2], c[nt][3]));
        }
        mx0 = fmaxf(mx0, __shfl_xor_sync(0xffffffffu, mx0, 1));
        mx0 = fmaxf(mx0, __shfl_xor_sync(0xffffffffu, mx0, 2));
        mx1 = fmaxf(mx1, __shfl_xor_sync(0xffffffffu, mx1, 1));
        mx1 = fmaxf(mx1, __shfl_xor_sync(0xffffffffu, mx1, 2));
        float s0 = 0.f, s1 = 0.f;
#pragma unroll
        for (int nt = 0; nt < 7; nt++) {
            c[nt][0] = __expf(c[nt][0] - mx0); s0 += c[nt][0];
            c[nt][1] = __expf(c[nt][1] - mx0); s0 += c[nt][1];
            c[nt][2] = __expf(c[nt][2] - mx1); s1 += c[nt][2];
            c[nt][3] = __expf(c[nt][3] - mx1); s1 += c[nt][3];
        }
        s0 += __shfl_xor_sync(0xffffffffu, s0, 1);
        s0 += __shfl_xor_sync(0xffffffffu, s0, 2);
        s1 += __shfl_xor_sync(0xffffffffu, s1, 1);
        s1 += __shfl_xor_sync(0xffffffffu, s1, 2);
        float i0 = 1.f / s0, i1 = 1.f / s1;
#pragma unroll
        for (int nt = 0; nt < 7; nt++) {
            c[nt][0] *= i0; c[nt][1] *= i0;
            c[nt][2] *= i1; c[nt][3] *= i1;
        }
    }

    // ---- O = P*V : P fragments packed from S accumulators ----
    float o[4][4];
#pragma unroll
    for (int nt = 0; nt < 4; nt++)
#pragma unroll
        for (int i = 0; i < 4; i++) o[nt][i] = 0.f;
#pragma unroll
    for (int kk = 0; kk < 4; kk++) {
        uint32_t a0, a1, a2, a3;
        if (kk < 3) {
            a0 = packh2(c[2 * kk][0],     c[2 * kk][1]);
            a1 = packh2(c[2 * kk][2],     c[2 * kk][3]);
            a2 = packh2(c[2 * kk + 1][0], c[2 * kk + 1][1]);
            a3 = packh2(c[2 * kk + 1][2], c[2 * kk + 1][3]);
        } else {
            a0 = packh2(c[6][0], c[6][1]);
            a1 = packh2(c[6][2], c[6][3]);
            a2 = 0u; a3 = 0u;
        }
        int col = kk * 16 + tig * 2;
#pragma unroll
        for (int nt = 0; nt < 4; nt++) {
            uint32_t b0 = *(uint32_t*)&Vt[h][nt * 8 + gid][col];
            uint32_t b1 = *(uint32_t*)&Vt[h][nt * 8 + gid][col + 8];
            mma16816(o[nt], a0, a1, a2, a3, b0, b1);
        }
    }
#pragma unroll
    for (int half_ = 0; half_ < 2; half_++) {
        int n = r0 + half_ * 8;
        if (n < 49) {
            size_t orow = ((size_t)w * 49 + n) * CH + head * HD;
#pragma unroll
            for (int nt = 0; nt < 4; nt++) {
                int d = nt * 8 + 2 * tig;
                __half2 h2 = __floats2half2_rn(o[nt][half_ * 2 + 0], o[nt][half_ * 2 + 1]);
                *(__half2*)&g_attn[orow + d] = h2;
            }
        }
    }
}

// ---------------- fp16 GEMM (R11 winner): 128x128, BK=64, 2-stage .cg, frag dbuf ----------
#define BM 128
#define BN 128
#define BK 64
#define STG_BYTES 16384          // 128*64*2
#define SMEM_GEMM (4 * STG_BYTES)

template <int EPI>
__global__ __launch_bounds__(256, 2)
void gemm_h(const __half* __restrict__ A, const __half* __restrict__ B,
            const float* __restrict__ bias, const float* __restrict__ res,
            void* __restrict__ Cv, int M, int N, int K) {
    extern __shared__ char smem[];
    uint32_t sA0 = (uint32_t)__cvta_generic_to_shared(smem);
    uint32_t sB0 = sA0 + 2 * STG_BYTES;
    int tid = threadIdx.x;
    int lane = tid & 31, warp = tid >> 5;
    int wm = (warp >> 2) * 64, wn = (warp & 3) * 32;
    int bm = blockIdx.y * BM, bn = blockIdx.x * BN;

    float acc[4][4][4];
#pragma unroll
    for (int i = 0; i < 4; i++)
#pragma unroll
        for (int j = 0; j < 4; j++)
#pragma unroll
            for (int k = 0; k < 4; k++) acc[i][j][k] = 0.f;

    int lr = tid >> 2, lc = tid & 3;
    const __half* Ab = A + (size_t)(bm + lr) * K + lc * 8;
    const __half* Bb = B + (size_t)(bn + lr) * K + lc * 8;
    uint32_t stA[4];
    {
        int r1 = lr, r2 = lr + 64;
        stA[0] = r1 * 128 + (((lc)     ^ (r1 & 7)) << 4);
        stA[1] = r1 * 128 + (((lc + 4) ^ (r1 & 7)) << 4);
        stA[2] = r2 * 128 + (((lc)     ^ (r2 & 7)) << 4);
        stA[3] = r2 * 128 + (((lc + 4) ^ (r2 & 7)) << 4);
    }

    uint32_t aOff[4], aXor[4];
#pragma unroll
    for (int mt = 0; mt < 4; mt++) {
        int r = wm + mt * 16 + (lane & 7) + (lane & 8);
        aOff[mt] = r * 128;
        aXor[mt] = (r & 7) << 4;
    }
    int aCs = (lane >> 4) & 1;
    uint32_t bOff[2], bXor[2];
#pragma unroll
    for (int p = 0; p < 2; p++) {
        int r = wn + p * 16 + (lane & 7) + ((lane >> 4) & 1) * 8;
        bOff[p] = r * 128;
        bXor[p] = (r & 7) << 4;
    }
    int bCs = (lane >> 3) & 1;

    int NIT = K / BK;
    {
#pragma unroll
        for (int i = 0; i < 4; i++) {
            cp16(sA0 + stA[i], Ab + ((i >> 1) ? (size_t)64 * K : 0) + ((i & 1) ? 32 : 0));
            cp16(sB0 + stA[i], Bb + ((i >> 1) ? (size_t)64 * K : 0) + ((i & 1) ? 32 : 0));
        }
        cp_commit();
    }
    for (int it = 0; it < NIT; ++it) {
        if (it + 1 < NIT) {
            uint32_t so = ((it + 1) & 1) * STG_BYTES;
            const __half* ap = Ab + (it + 1) * BK;
            const __half* bp = Bb + (it + 1) * BK;
#pragma unroll
            for (int i = 0; i < 4; i++) {
                cp16(sA0 + so + stA[i], ap + ((i >> 1) ? (size_t)64 * K : 0) + ((i & 1) ? 32 : 0));
                cp16(sB0 + so + stA[i], bp + ((i >> 1) ? (size_t)64 * K : 0) + ((i & 1) ? 32 : 0));
            }
        }
        cp_commit();
        cp_wait1();
        __syncthreads();
        uint32_t aBase = sA0 + (it & 1) * STG_BYTES;
        uint32_t bBase = sB0 + (it & 1) * STG_BYTES;

        uint32_t a[2][4][4], b[2][2][4];
        {
            uint32_t cA = ((aCs) << 4);
            uint32_t cB = ((bCs) << 4);
#pragma unroll
            for (int mt = 0; mt < 4; mt++)
                ldsm4(a[0][mt], aBase + aOff[mt] + (cA ^ aXor[mt]));
#pragma unroll
            for (int p = 0; p < 2; p++)
                ldsm4(b[0][p], bBase + bOff[p] + (cB ^ bXor[p]));
        }
#pragma unroll
        for (int kk = 0; kk < 4; kk++) {
            int cur = kk & 1, nxt = cur ^ 1;
            if (kk < 3) {
                uint32_t cA = ((2 * (kk + 1) + aCs) << 4);
                uint32_t cB = ((2 * (kk + 1) + bCs) << 4);
#pragma unroll
                for (int mt = 0; mt < 4; mt++)
                    ldsm4(a[nxt][mt], aBase + aOff[mt] + (cA ^ aXor[mt]));
#pragma unroll
                for (int p = 0; p < 2; p++)
                    ldsm4(b[nxt][p], bBase + bOff[p] + (cB ^ bXor[p]));
            }
#pragma unroll
            for (int mt = 0; mt < 4; mt++)
#pragma unroll
                for (int nt = 0; nt < 4; nt++)
                    mma16816(acc[mt][nt], a[cur][mt][0], a[cur][mt][1],
                             a[cur][mt][2], a[cur][mt][3],
                             b[cur][nt >> 1][(nt & 1) * 2], b[cur][nt >> 1][(nt & 1) * 2 + 1]);
        }
        __syncthreads();
    }

    int gid = lane >> 2, tig = lane & 3;
#pragma unroll
    for (int mt = 0; mt < 4; mt++) {
#pragma unroll
        for (int half_ = 0; half_ < 2; half_++) {
            int m = bm + wm + mt * 16 + gid + half_ * 8;
            size_t drow;
            if (EPI == 2) {
                int wnd = m / 49, n = m - wnd * 49;
                int bb = wnd >> 4, wl = wnd & 15;
                int wh = wl >> 2, ww = wl & 3;
                int ii = n / 7, jj = n - ii * 7;
                int h_ = wh * 7 + ii + 3; if (h_ >= 28) h_ -= 28;
                int w_ = ww * 7 + jj + 3; if (w_ >= 28) w_ -= 28;
                drow = (size_t)(bb * 784 + h_ * 28 + w_);
            } else {
                drow = (size_t)m;
            }
#pragma unroll
            for (int nt = 0; nt < 4; nt++) {
                int cc = bn + wn + nt * 8 + 2 * tig;
                float v0 = acc[mt][nt][half_ * 2 + 0] + bias[cc];
                float v1 = acc[mt][nt][half_ * 2 + 1] + bias[cc + 1];
                if (EPI == 1) { v0 = gelu_exact(v0); v1 = gelu_exact(v1); }
                if (EPI == 2 || EPI == 3) {
                    const float* rrow = res + drow * N;
                    v0 += rrow[cc]; v1 += rrow[cc + 1];
                    float2 o; o.x = v0; o.y = v1;
                    *(float2*)&((float*)Cv)[drow * N + cc] = o;
                } else {
                    __half2 h2 = __floats2half2_rn(v0, v1);
                    *(__half2*)&((__half*)Cv)[drow * N + cc] = h2;
                }
            }
        }
    }
}

// ---------------- launch ----------------
extern "C" void kernel_launch(void* const* d_in, const int* in_sizes, int n_in,
                              void* d_out, int out_size) {
    const float* x      = (const float*)d_in[0];
    const float* ln1_s  = (const float*)d_in[1];
    const float* ln1_b  = (const float*)d_in[2];
    const float* qkv_w  = (const float*)d_in[3];
    const float* qkv_b  = (const float*)d_in[4];
    const float* qkv_la = (const float*)d_in[5];
    const float* qkv_lb = (const float*)d_in[6];
    const float* rpb    = (const float*)d_in[7];
    const float* proj_w = (const float*)d_in[8];
    const float* proj_b = (const float*)d_in[9];
    const float* proj_la= (const float*)d_in[10];
    const float* proj_lb= (const float*)d_in[11];
    const float* ln2_s  = (const float*)d_in[12];
    const float* ln2_b  = (const float*)d_in[13];
    const float* fc1_w  = (const float*)d_in[14];
    const float* fc1_b  = (const float*)d_in[15];
    const float* fc1_la = (const float*)d_in[16];
    const float* fc1_lb = (const float*)d_in[17];
    const float* fc2_w  = (const float*)d_in[18];
    const float* fc2_b  = (const float*)d_in[19];
    const float* fc2_la = (const float*)d_in[20];
    const float* fc2_lb = (const float*)d_in[21];
    float* out = (float*)d_out;

    __half *wqkv, *wproj, *wfc1, *wfc2, *xw, *qkv, *attn, *xn2, *hb;
    float *x2;
    cudaGetSymbolAddress((void**)&wqkv,  g_wqkv);
    cudaGetSymbolAddress((void**)&wproj, g_wproj);
    cudaGetSymbolAddress((void**)&wfc1,  g_wfc1);
    cudaGetSymbolAddress((void**)&wfc2,  g_wfc2);
    cudaGetSymbolAddress((void**)&xw,    g_xw);
    cudaGetSymbolAddress((void**)&qkv,   g_qkv);
    cudaGetSymbolAddress((void**)&attn,  g_attn);
    cudaGetSymbolAddress((void**)&x2,    g_x2);
    cudaGetSymbolAddress((void**)&xn2,   g_xn2);
    cudaGetSymbolAddress((void**)&hb,    g_hbuf);

    cudaFuncSetAttribute(gemm_h<0>, cudaFuncAttributeMaxDynamicSharedMemorySize, SMEM_GEMM);
    cudaFuncSetAttribute(gemm_h<1>, cudaFuncAttributeMaxDynamicSharedMemorySize, SMEM_GEMM);
    cudaFuncSetAttribute(gemm_h<2>, cudaFuncAttributeMaxDynamicSharedMemorySize, SMEM_GEMM);
    cudaFuncSetAttribute(gemm_h<3>, cudaFuncAttributeMaxDynamicSharedMemorySize, SMEM_GEMM);

    // 1) fold LoRA into weights + bias table (one launch)
    fuse_all_kernel<<<12544, 256>>>(qkv_w, qkv_la, qkv_lb, wqkv,
                                    proj_w, proj_la, proj_lb, wproj,
                                    fc1_w, fc1_la, fc1_lb, wfc1,
                                    fc2_w, fc2_la, fc2_lb, wfc2, rpb);

    // 2) LN1 + shift + window partition (warp-per-row)
    ln_kernel<true><<<TOK / 8, 256>>>(x, ln1_s, ln1_b, xw);

    // 3) QKV GEMM
    gemm_h<0><<<dim3(C3 / BN, TOK / BM), 256, SMEM_GEMM>>>(xw, wqkv, qkv_b, nullptr, qkv, TOK, C3, CH);

    // 4) windowed attention (2 heads per block)
    attn_kernel<<<dim3(NWIN, NHD / 2), 256>>>();

    // 5) proj GEMM + window reverse + reverse shift + residual
    gemm_h<2><<<dim3(CH / BN, TOK / BM), 256, SMEM_GEMM>>>(attn, wproj, proj_b, x, x2, TOK, CH, CH);

    // 6) LN2 (warp-per-row)
    ln_kernel<false><<<TOK / 8, 256>>>(x2, ln2_s, ln2_b, xn2);

    // 7) fc1 + GELU
    gemm_h<1><<<dim3(FF / BN, TOK / BM), 256, SMEM_GEMM>>>(xn2, wfc1, fc1_b, nullptr, hb, TOK, FF, CH);

    // 8) fc2 + residual -> out
    gemm_h<3><<<dim3(CH / BN, TOK / BM), 256, SMEM_GEMM>>>(hb, wfc2, fc2_b, x2, out, TOK, CH, FF);
}

// round 15
// speedup vs baseline: 1.0154x; 1.0154x over previous
#include <cuda_runtime.h>
#include <cuda_fp16.h>
#include <math.h>
#include <stdint.h>

// ---------------- problem constants ----------------
#define TOK   50176
#define CH    512
#define C3    1536
#define FF    2048
#define NHD   16
#define HD    32
#define NWIN  1024

// ---------------- device scratch ----------------
__device__ __half g_wqkv[C3 * CH];            // effective weights, [N][K] K-major
__device__ __half g_wproj[CH * CH];
__device__ __half g_wfc1[FF * CH];
__device__ __half g_wfc2[CH * FF];
__device__ __half g_xw  [(size_t)TOK * CH];
__device__ __half g_qkv [(size_t)TOK * C3];
__device__ __half g_attn[(size_t)TOK * CH];
__device__ float  g_x2  [(size_t)TOK * CH];
__device__ __half g_xn2 [(size_t)TOK * CH];
__device__ __half g_hbuf[(size_t)TOK * FF];
__device__ float  g_bias[16 * 16 * 49 * 52]; // combined rel-pos bias + shift mask

// ---------------- helpers ----------------
__device__ __forceinline__ float gelu_exact(float x) {
    return 0.5f * x * (1.0f + erff(x * 0.70710678118654752f));
}
__device__ __forceinline__ void cp16(uint32_t saddr, const void* g) {
    asm volatile("cp.async.cg.shared.global [%0], [%1], 16;" :: "r"(saddr), "l"(g));
}
__device__ __forceinline__ void cp_commit() { asm volatile("cp.async.commit_group;"); }
__device__ __forceinline__ void cp_wait1()  { asm volatile("cp.async.wait_group 1;"); }

__device__ __forceinline__ void mma16816(float c[4],
        uint32_t a0, uint32_t a1, uint32_t a2, uint32_t a3,
        uint32_t b0, uint32_t b1) {
    asm volatile("mma.sync.aligned.m16n8k16.row.col.f32.f16.f16.f32 "
        "{%0,%1,%2,%3}, {%4,%5,%6,%7}, {%8,%9}, {%0,%1,%2,%3};"
        : "+f"(c[0]), "+f"(c[1]), "+f"(c[2]), "+f"(c[3])
        : "r"(a0), "r"(a1), "r"(a2), "r"(a3), "r"(b0), "r"(b1));
}
__device__ __forceinline__ void ldsm4(uint32_t* r, uint32_t addr) {
    asm volatile("ldmatrix.sync.aligned.m8n8.x4.shared.b16 {%0,%1,%2,%3}, [%4];"
        : "=r"(r[0]), "=r"(r[1]), "=r"(r[2]), "=r"(r[3]) : "r"(addr));
}
__device__ __forceinline__ void ldsm4t(uint32_t* r, uint32_t addr) {
    asm volatile("ldmatrix.sync.aligned.m8n8.x4.trans.shared.b16 {%0,%1,%2,%3}, [%4];"
        : "=r"(r[0]), "=r"(r[1]), "=r"(r[2]), "=r"(r[3]) : "r"(addr));
}
__device__ __forceinline__ uint32_t packh2(float a, float b) {
    __half2 h = __floats2half2_rn(a, b);
    return *(uint32_t*)&h;
}

// ---------------- merged preprocessing: LoRA weight folding + bias table ----------------
__global__ void fuse_all_kernel(
        const float* __restrict__ W0, const float* __restrict__ la0, const float* __restrict__ lb0, __half* __restrict__ o0,
        const float* __restrict__ W1, const float* __restrict__ la1, const float* __restrict__ lb1, __half* __restrict__ o1,
        const float* __restrict__ W2, const float* __restrict__ la2, const float* __restrict__ lb2, __half* __restrict__ o2,
        const float* __restrict__ W3, const float* __restrict__ la3, const float* __restrict__ lb3, __half* __restrict__ o3,
        const float* __restrict__ rpb) {
    int b = blockIdx.x;
    if (b >= 12288) {
        int u = b - 12288;
        int wl = u >> 4, hh = u & 15;
        int wh = wl >> 2, ww = wl & 3;
        float* dst = g_bias + ((size_t)(wl * 16 + hh)) * 49 * 52;
        for (int idx = threadIdx.x; idx < 49 * 52; idx += 256) {
            int n = idx / 52, m = idx - (idx / 52) * 52;
            float v = 0.f;
            if (m < 49) {
                int i1 = n / 7, j1 = n - i1 * 7;
                int i2 = m / 7, j2 = m - i2 * 7;
                v = rpb[((i1 - i2 + 6) * 13 + (j1 - j2 + 6)) * NHD + hh];
                int hs1 = wh * 7 + i1, ws1 = ww * 7 + j1;
                int hs2 = wh * 7 + i2, ws2 = ww * 7 + j2;
                int r1 = (hs1 < 21 ? 0 : (hs1 < 25 ? 1 : 2)) * 3 + (ws1 < 21 ? 0 : (ws1 < 25 ? 1 : 2));
                int r2 = (hs2 < 21 ? 0 : (hs2 < 25 ? 1 : 2)) * 3 + (ws2 < 21 ? 0 : (ws2 < 25 ? 1 : 2));
                if (r1 != r2) v -= 100.f;
            }
            dst[idx] = v;
        }
        return;
    }
    const float *W, *la, *lb; __half* o; int K, base;
    if (b < 3072)      { W = W0; la = la0; lb = lb0; o = o0; K = CH; base = 0; }
    else if (b < 4096) { W = W1; la = la1; lb = lb1; o = o1; K = CH; base = 3072; }
    else if (b < 8192) { W = W2; la = la2; lb = lb2; o = o2; K = CH; base = 4096; }
    else               { W = W3; la = la3; lb = lb3; o = o3; K = FF; base = 8192; }
    int idx = (b - base) * 256 + threadIdx.x;
    int n = idx / K, k = idx - n * K;
    float acc = W[idx];
#pragma unroll
    for (int r = 0; r < 16; r++) acc += lb[n * 16 + r] * la[(size_t)r * K + k];
    o[idx] = __float2half(acc);
}

// ---------------- layernorm, warp-per-row (no barriers, no smem) ----------------
template <bool GATHER>
__global__ __launch_bounds__(256) void ln_kernel(const float* __restrict__ x,
                          const float* __restrict__ s, const float* __restrict__ b,
                          __half* __restrict__ out) {
    int warp = threadIdx.x >> 5, lane = threadIdx.x & 31;
    int t = blockIdx.x * 8 + warp;
    const float* row;
    if (GATHER) {
        int wnd = t / 49, n = t - wnd * 49;
        int bb = wnd >> 4, wl = wnd & 15;
        int wh = wl >> 2, ww = wl & 3;
        int i = n / 7, j = n - i * 7;
        int h = wh * 7 + i + 3; if (h >= 28) h -= 28;
        int wc = ww * 7 + j + 3; if (wc >= 28) wc -= 28;
        row = x + ((size_t)bb * 784 + h * 28 + wc) * CH;
    } else {
        row = x + (size_t)t * CH;
    }
    float4 v[4];
    float sum = 0.f, sq = 0.f;
#pragma unroll
    for (int i = 0; i < 4; i++) {
        v[i] = ((const float4*)row)[lane + 32 * i];
        sum += v[i].x + v[i].y + v[i].z + v[i].w;
        sq  += v[i].x * v[i].x + v[i].y * v[i].y + v[i].z * v[i].z + v[i].w * v[i].w;
    }
#pragma unroll
    for (int o = 16; o > 0; o >>= 1) {
        sum += __shfl_xor_sync(0xffffffffu, sum, o);
        sq  += __shfl_xor_sync(0xffffffffu, sq, o);
    }
    float mean = sum * (1.f / CH);
    float var  = sq * (1.f / CH) - mean * mean;
    float rstd = rsqrtf(var + 1e-5f);
    __half* orow = out + (size_t)t * CH;
#pragma unroll
    for (int i = 0; i < 4; i++) {
        float4 sv = ((const float4*)s)[lane + 32 * i];
        float4 bv = ((const float4*)b)[lane + 32 * i];
        __half2 h0 = __floats2half2_rn((v[i].x - mean) * rstd * sv.x + bv.x,
                                       (v[i].y - mean) * rstd * sv.y + bv.y);
        __half2 h1 = __floats2half2_rn((v[i].z - mean) * rstd * sv.z + bv.z,
                                       (v[i].w - mean) * rstd * sv.w + bv.w);
        uint2 o2; o2.x = *(uint32_t*)&h0; o2.y = *(uint32_t*)&h1;
        ((uint2*)orow)[lane + 32 * i] = o2;
    }
}

// ---------------- windowed attention: 2 heads/block, ldmatrix.trans V, reg-resident P -------
__global__ __launch_bounds__(256) void attn_kernel() {
    __shared__ __half Qs[2][64][40];   // rows 49..63 zeroed
    __shared__ __half Ks[2][56][40];   // rows 49..55 garbage ok (masked)
    __shared__ __half Vs[2][64][40];   // natural [m][d]; rows 49..63 zeroed
    int w = blockIdx.x, hp = blockIdx.y;
    int tid = threadIdx.x;
    int lane = tid & 31, warp = tid >> 5;
    int h = warp >> 2, lw = warp & 3;
    int gid = lane >> 2, tig = lane & 3;
    int head = hp * 2 + h;
    const float* Bc = g_bias + ((size_t)((w & 15) * 16 + head)) * 49 * 52;

    // ---- load q/k/v (pure uint4 vector stores) ----
    size_t base = (size_t)w * 49 * C3 + (size_t)hp * 64;
    for (int idx = tid; idx < 49 * 8; idx += 256) {
        int n = idx >> 3, part = idx & 7;
        int hs = part >> 2, dq = (part & 3) * 8;
        size_t off = base + (size_t)n * C3 + hs * 32 + dq;
        *(uint4*)&Qs[hs][n][dq] = *(const uint4*)&g_qkv[off];
        *(uint4*)&Ks[hs][n][dq] = *(const uint4*)&g_qkv[off + 512];
        *(uint4*)&Vs[hs][n][dq] = *(const uint4*)&g_qkv[off + 1024];
    }
    // zero pad rows 49..63 of Qs and Vs (contiguous per head: 15*40 halves = 300 uints)
    for (int i = tid; i < 1200; i += 256) {
        int a = i / 300, r = i - a * 300;
        uint32_t* p = (a < 2) ? (uint32_t*)&Qs[a][49][0] : (uint32_t*)&Vs[a - 2][49][0];
        p[r] = 0;
    }
    __syncthreads();

    // ---- S = Q*K^T ----
    float c[7][4];
#pragma unroll
    for (int nt = 0; nt < 7; nt++)
#pragma unroll
        for (int i = 0; i < 4; i++) c[nt][i] = 0.f;
    int r0 = lw * 16 + gid;
    int r1 = r0 + 8;
#pragma unroll
    for (int kk = 0; kk < 2; kk++) {
        int col = kk * 16 + tig * 2;
        uint32_t a0 = *(uint32_t*)&Qs[h][r0][col];
        uint32_t a1 = *(uint32_t*)&Qs[h][r1][col];
        uint32_t a2 = *(uint32_t*)&Qs[h][r0][col + 8];
        uint32_t a3 = *(uint32_t*)&Qs[h][r1][col + 8];
#pragma unroll
        for (int nt = 0; nt < 7; nt++) {
            uint32_t b0 = *(uint32_t*)&Ks[h][nt * 8 + gid][col];
            uint32_t b1 = *(uint32_t*)&Ks[h][nt * 8 + gid][col + 8];
            mma16816(c[nt], a0, a1, a2, a3, b0, b1);
        }
    }

    // ---- scale + bias + mask ----
    const float scale = 0.1767766952966369f;
    bool rv0 = r0 < 49, rv1 = r1 < 49;
#pragma unroll
    for (int nt = 0; nt < 7; nt++) {
        int cc = nt * 8 + 2 * tig;
#pragma unroll
        for (int e = 0; e < 2; e++) {
            int col = cc + e;
            bool cv = col < 49;
            c[nt][e]     = (rv0 && cv) ? c[nt][e]     * scale + Bc[r0 * 52 + col] : -1e30f;
            c[nt][2 + e] = (rv1 && cv) ? c[nt][2 + e] * scale + Bc[r1 * 52 + col] : -1e30f;
        }
    }

    // ---- softmax: quad shuffle reduction ----
    {
        float mx0 = -1e30f, mx1 = -1e30f;
#pragma unroll
        for (int nt = 0; nt < 7; nt++) {
            mx0 = fmaxf(mx0, fmaxf(c[nt][0], c[nt][1]));
            mx1 = fmaxf(mx1, fmaxf(c[nt][2], c[nt][3]));
        }
        mx0 = fmaxf(mx0, __shfl_xor_sync(0xffffffffu, mx0, 1));
        mx0 = fmaxf(mx0, __shfl_xor_sync(0xffffffffu, mx0, 2));
        mx1 = fmaxf(mx1, __shfl_xor_sync(0xffffffffu, mx1, 1));
        mx1 = fmaxf(mx1, __shfl_xor_sync(0xffffffffu, mx1, 2));
        float s0 = 0.f, s1 = 0.f;
#pragma unroll
        for (int nt = 0; nt < 7; nt++) {
            c[nt][0] = __expf(c[nt][0] - mx0); s0 += c[nt][0];
            c[nt][1] = __expf(c[nt][1] - mx0); s0 += c[nt][1];
            c[nt][2] = __expf(c[nt][2] - mx1); s1 += c[nt][2];
            c[nt][3] = __expf(c[nt][3] - mx1); s1 += c[nt][3];
        }
        s0 += __shfl_xor_sync(0xffffffffu, s0, 1);
        s0 += __shfl_xor_sync(0xffffffffu, s0, 2);
        s1 += __shfl_xor_sync(0xffffffffu, s1, 1);
        s1 += __shfl_xor_sync(0xffffffffu, s1, 2);
        float i0 = 1.f / s0, i1 = 1.f / s1;
#pragma unroll
        for (int nt = 0; nt < 7; nt++) {
            c[nt][0] *= i0; c[nt][1] *= i0;
            c[nt][2] *= i1; c[nt][3] *= i1;
        }
    }

    // ---- O = P*V : B fragments via ldmatrix.trans on natural-layout Vs ----
    // lane address: row = k0 + (lane&15), col = (lane>>4)*8 (+n0)
    uint32_t vaddr = (uint32_t)__cvta_generic_to_shared(&Vs[h][0][0])
                   + (uint32_t)(lane & 15) * 80 + (uint32_t)(lane >> 4) * 16;
    float o[4][4];
#pragma unroll
    for (int nt = 0; nt < 4; nt++)
#pragma unroll
        for (int i = 0; i < 4; i++) o[nt][i] = 0.f;
#pragma unroll
    for (int kk = 0; kk < 4; kk++) {
        uint32_t a0, a1, a2, a3;
        if (kk < 3) {
            a0 = packh2(c[2 * kk][0],     c[2 * kk][1]);
            a1 = packh2(c[2 * kk][2],     c[2 * kk][3]);
            a2 = packh2(c[2 * kk + 1][0], c[2 * kk + 1][1]);
            a3 = packh2(c[2 * kk + 1][2], c[2 * kk + 1][3]);
        } else {
            a0 = packh2(c[6][0], c[6][1]);
            a1 = packh2(c[6][2], c[6][3]);
            a2 = 0u; a3 = 0u;
        }
        uint32_t b01[4], b23[4];
        ldsm4t(b01, vaddr + (uint32_t)kk * 1280);        // n 0..15  (d 0..15)
        ldsm4t(b23, vaddr + (uint32_t)kk * 1280 + 32);   // n 16..31 (d 16..31)
        mma16816(o[0], a0, a1, a2, a3, b01[0], b01[1]);
        mma16816(o[1], a0, a1, a2, a3, b01[2], b01[3]);
        mma16816(o[2], a0, a1, a2, a3, b23[0], b23[1]);
        mma16816(o[3], a0, a1, a2, a3, b23[2], b23[3]);
    }
#pragma unroll
    for (int half_ = 0; half_ < 2; half_++) {
        int n = r0 + half_ * 8;
        if (n < 49) {
            size_t orow = ((size_t)w * 49 + n) * CH + head * HD;
#pragma unroll
            for (int nt = 0; nt < 4; nt++) {
                int d = nt * 8 + 2 * tig;
                __half2 h2 = __floats2half2_rn(o[nt][half_ * 2 + 0], o[nt][half_ * 2 + 1]);
                *(__half2*)&g_attn[orow + d] = h2;
            }
        }
    }
}

// ---------------- fp16 GEMM (R11 winner): 128x128, BK=64, 2-stage .cg, frag dbuf ----------
#define BM 128
#define BN 128
#define BK 64
#define STG_BYTES 16384          // 128*64*2
#define SMEM_GEMM (4 * STG_BYTES)

template <int EPI>
__global__ __launch_bounds__(256, 2)
void gemm_h(const __half* __restrict__ A, const __half* __restrict__ B,
            const float* __restrict__ bias, const float* __restrict__ res,
            void* __restrict__ Cv, int M, int N, int K) {
    extern __shared__ char smem[];
    uint32_t sA0 = (uint32_t)__cvta_generic_to_shared(smem);
    uint32_t sB0 = sA0 + 2 * STG_BYTES;
    int tid = threadIdx.x;
    int lane = tid & 31, warp = tid >> 5;
    int wm = (warp >> 2) * 64, wn = (warp & 3) * 32;
    int bm = blockIdx.y * BM, bn = blockIdx.x * BN;

    float acc[4][4][4];
#pragma unroll
    for (int i = 0; i < 4; i++)
#pragma unroll
        for (int j = 0; j < 4; j++)
#pragma unroll
            for (int k = 0; k < 4; k++) acc[i][j][k] = 0.f;

    int lr = tid >> 2, lc = tid & 3;
    const __half* Ab = A + (size_t)(bm + lr) * K + lc * 8;
    const __half* Bb = B + (size_t)(bn + lr) * K + lc * 8;
    uint32_t stA[4];
    {
        int r1 = lr, r2 = lr + 64;
        stA[0] = r1 * 128 + (((lc)     ^ (r1 & 7)) << 4);
        stA[1] = r1 * 128 + (((lc + 4) ^ (r1 & 7)) << 4);
        stA[2] = r2 * 128 + (((lc)     ^ (r2 & 7)) << 4);
        stA[3] = r2 * 128 + (((lc + 4) ^ (r2 & 7)) << 4);
    }

    uint32_t aOff[4], aXor[4];
#pragma unroll
    for (int mt = 0; mt < 4; mt++) {
        int r = wm + mt * 16 + (lane & 7) + (lane & 8);
        aOff[mt] = r * 128;
        aXor[mt] = (r & 7) << 4;
    }
    int aCs = (lane >> 4) & 1;
    uint32_t bOff[2], bXor[2];
#pragma unroll
    for (int p = 0; p < 2; p++) {
        int r = wn + p * 16 + (lane & 7) + ((lane >> 4) & 1) * 8;
        bOff[p] = r * 128;
        bXor[p] = (r & 7) << 4;
    }
    int bCs = (lane >> 3) & 1;

    int NIT = K / BK;
    {
#pragma unroll
        for (int i = 0; i < 4; i++) {
            cp16(sA0 + stA[i], Ab + ((i >> 1) ? (size_t)64 * K : 0) + ((i & 1) ? 32 : 0));
            cp16(sB0 + stA[i], Bb + ((i >> 1) ? (size_t)64 * K : 0) + ((i & 1) ? 32 : 0));
        }
        cp_commit();
    }
    for (int it = 0; it < NIT; ++it) {
        if (it + 1 < NIT) {
            uint32_t so = ((it + 1) & 1) * STG_BYTES;
            const __half* ap = Ab + (it + 1) * BK;
            const __half* bp = Bb + (it + 1) * BK;
#pragma unroll
            for (int i = 0; i < 4; i++) {
                cp16(sA0 + so + stA[i], ap + ((i >> 1) ? (size_t)64 * K : 0) + ((i & 1) ? 32 : 0));
                cp16(sB0 + so + stA[i], bp + ((i >> 1) ? (size_t)64 * K : 0) + ((i & 1) ? 32 : 0));
            }
        }
        cp_commit();
        cp_wait1();
        __syncthreads();
        uint32_t aBase = sA0 + (it & 1) * STG_BYTES;
        uint32_t bBase = sB0 + (it & 1) * STG_BYTES;

        uint32_t a[2][4][4], b[2][2][4];
        {
            uint32_t cA = ((aCs) << 4);
            uint32_t cB = ((bCs) << 4);
#pragma unroll
            for (int mt = 0; mt < 4; mt++)
                ldsm4(a[0][mt], aBase + aOff[mt] + (cA ^ aXor[mt]));
#pragma unroll
            for (int p = 0; p < 2; p++)
                ldsm4(b[0][p], bBase + bOff[p] + (cB ^ bXor[p]));
        }
#pragma unroll
        for (int kk = 0; kk < 4; kk++) {
            int cur = kk & 1, nxt = cur ^ 1;
            if (kk < 3) {
                uint32_t cA = ((2 * (kk + 1) + aCs) << 4);
                uint32_t cB = ((2 * (kk + 1) + bCs) << 4);
#pragma unroll
                for (int mt = 0; mt < 4; mt++)
                    ldsm4(a[nxt][mt], aBase + aOff[mt] + (cA ^ aXor[mt]));
#pragma unroll
                for (int p = 0; p < 2; p++)
                    ldsm4(b[nxt][p], bBase + bOff[p] + (cB ^ bXor[p]));
            }
#pragma unroll
            for (int mt = 0; mt < 4; mt++)
#pragma unroll
                for (int nt = 0; nt < 4; nt++)
                    mma16816(acc[mt][nt], a[cur][mt][0], a[cur][mt][1],
                             a[cur][mt][2], a[cur][mt][3],
                             b[cur][nt >> 1][(nt & 1) * 2], b[cur][nt >> 1][(nt & 1) * 2 + 1]);
        }
        __syncthreads();
    }

    int gid = lane >> 2, tig = lane & 3;
#pragma unroll
    for (int mt = 0; mt < 4; mt++) {
#pragma unroll
        for (int half_ = 0; half_ < 2; half_++) {
            int m = bm + wm + mt * 16 + gid + half_ * 8;
            size_t drow;
            if (EPI == 2) {
                int wnd = m / 49, n = m - wnd * 49;
                int bb = wnd >> 4, wl = wnd & 15;
                int wh = wl >> 2, ww = wl & 3;
                int ii = n / 7, jj = n - ii * 7;
                int h_ = wh * 7 + ii + 3; if (h_ >= 28) h_ -= 28;
                int w_ = ww * 7 + jj + 3; if (w_ >= 28) w_ -= 28;
                drow = (size_t)(bb * 784 + h_ * 28 + w_);
            } else {
                drow = (size_t)m;
            }
#pragma unroll
            for (int nt = 0; nt < 4; nt++) {
                int cc = bn + wn + nt * 8 + 2 * tig;
                float v0 = acc[mt][nt][half_ * 2 + 0] + bias[cc];
                float v1 = acc[mt][nt][half_ * 2 + 1] + bias[cc + 1];
                if (EPI == 1) { v0 = gelu_exact(v0); v1 = gelu_exact(v1); }
                if (EPI == 2 || EPI == 3) {
                    const float* rrow = res + drow * N;
                    v0 += rrow[cc]; v1 += rrow[cc + 1];
                    float2 o; o.x = v0; o.y = v1;
                    *(float2*)&((float*)Cv)[drow * N + cc] = o;
                } else {
                    __half2 h2 = __floats2half2_rn(v0, v1);
                    *(__half2*)&((__half*)Cv)[drow * N + cc] = h2;
                }
            }
        }
    }
}

// ---------------- launch ----------------
extern "C" void kernel_launch(void* const* d_in, const int* in_sizes, int n_in,
                              void* d_out, int out_size) {
    const float* x      = (const float*)d_in[0];
    const float* ln1_s  = (const float*)d_in[1];
    const float* ln1_b  = (const float*)d_in[2];
    const float* qkv_w  = (const float*)d_in[3];
    const float* qkv_b  = (const float*)d_in[4];
    const float* qkv_la = (const float*)d_in[5];
    const float* qkv_lb = (const float*)d_in[6];
    const float* rpb    = (const float*)d_in[7];
    const float* proj_w = (const float*)d_in[8];
    const float* proj_b = (const float*)d_in[9];
    const float* proj_la= (const float*)d_in[10];
    const float* proj_lb= (const float*)d_in[11];
    const float* ln2_s  = (const float*)d_in[12];
    const float* ln2_b  = (const float*)d_in[13];
    const float* fc1_w  = (const float*)d_in[14];
    const float* fc1_b  = (const float*)d_in[15];
    const float* fc1_la = (const float*)d_in[16];
    const float* fc1_lb = (const float*)d_in[17];
    const float* fc2_w  = (const float*)d_in[18];
    const float* fc2_b  = (const float*)d_in[19];
    const float* fc2_la = (const float*)d_in[20];
    const float* fc2_lb = (const float*)d_in[21];
    float* out = (float*)d_out;

    __half *wqkv, *wproj, *wfc1, *wfc2, *xw, *qkv, *attn, *xn2, *hb;
    float *x2;
    cudaGetSymbolAddress((void**)&wqkv,  g_wqkv);
    cudaGetSymbolAddress((void**)&wproj, g_wproj);
    cudaGetSymbolAddress((void**)&wfc1,  g_wfc1);
    cudaGetSymbolAddress((void**)&wfc2,  g_wfc2);
    cudaGetSymbolAddress((void**)&xw,    g_xw);
    cudaGetSymbolAddress((void**)&qkv,   g_qkv);
    cudaGetSymbolAddress((void**)&attn,  g_attn);
    cudaGetSymbolAddress((void**)&x2,    g_x2);
    cudaGetSymbolAddress((void**)&xn2,   g_xn2);
    cudaGetSymbolAddress((void**)&hb,    g_hbuf);

    cudaFuncSetAttribute(gemm_h<0>, cudaFuncAttributeMaxDynamicSharedMemorySize, SMEM_GEMM);
    cudaFuncSetAttribute(gemm_h<1>, cudaFuncAttributeMaxDynamicSharedMemorySize, SMEM_GEMM);
    cudaFuncSetAttribute(gemm_h<2>, cudaFuncAttributeMaxDynamicSharedMemorySize, SMEM_GEMM);
    cudaFuncSetAttribute(gemm_h<3>, cudaFuncAttributeMaxDynamicSharedMemorySize, SMEM_GEMM);

    // 1) fold LoRA into weights + bias table (one launch)
    fuse_all_kernel<<<12544, 256>>>(qkv_w, qkv_la, qkv_lb, wqkv,
                                    proj_w, proj_la, proj_lb, wproj,
                                    fc1_w, fc1_la, fc1_lb, wfc1,
                                    fc2_w, fc2_la, fc2_lb, wfc2, rpb);

    // 2) LN1 + shift + window partition (warp-per-row)
    ln_kernel<true><<<TOK / 8, 256>>>(x, ln1_s, ln1_b, xw);

    // 3) QKV GEMM
    gemm_h<0><<<dim3(C3 / BN, TOK / BM), 256, SMEM_GEMM>>>(xw, wqkv, qkv_b, nullptr, qkv, TOK, C3, CH);

    // 4) windowed attention (2 heads per block, ldmatrix.trans V)
    attn_kernel<<<dim3(NWIN, NHD / 2), 256>>>();

    // 5) proj GEMM + window reverse + reverse shift + residual
    gemm_h<2><<<dim3(CH / BN, TOK / BM), 256, SMEM_GEMM>>>(attn, wproj, proj_b, x, x2, TOK, CH, CH);

    // 6) LN2 (warp-per-row)
    ln_kernel<false><<<TOK / 8, 256>>>(x2, ln2_s, ln2_b, xn2);

    // 7) fc1 + GELU
    gemm_h<1><<<dim3(FF / BN, TOK / BM), 256, SMEM_GEMM>>>(xn2, wfc1, fc1_b, nullptr, hb, TOK, FF, CH);

    // 8) fc2 + residual -> out
    gemm_h<3><<<dim3(CH / BN, TOK / BM), 256, SMEM_GEMM>>>(hb, wfc2, fc2_b, x2, out, TOK, CH, FF);
}

// round 16
// speedup vs baseline: 1.0304x; 1.0148x over previous
#include <cuda_runtime.h>
#include <cuda_fp16.h>
#include <math.h>
#include <stdint.h>

// ---------------- problem constants ----------------
#define TOK   50176
#define CH    512
#define C3    1536
#define FF    2048
#define NHD   16
#define HD    32
#define NWIN  1024

// ---------------- device scratch ----------------
__device__ __half g_wqkv[C3 * CH];            // effective weights, [N][K] K-major
__device__ __half g_wproj[CH * CH];
__device__ __half g_wfc1[FF * CH];
__device__ __half g_wfc2[CH * FF];
__device__ __half g_xw  [(size_t)TOK * CH];
__device__ __half g_qkv [(size_t)TOK * C3];
__device__ __half g_attn[(size_t)TOK * CH];
__device__ float  g_x2  [(size_t)TOK * CH];
__device__ __half g_xn2 [(size_t)TOK * CH];
__device__ __half g_hbuf[(size_t)TOK * FF];
__device__ __half g_biash[16 * 16 * 49 * 52]; // combined rel-pos bias + shift mask (fp16)

// ---------------- helpers ----------------
__device__ __forceinline__ float gelu_exact(float x) {
    return 0.5f * x * (1.0f + erff(x * 0.70710678118654752f));
}
__device__ __forceinline__ void cp16(uint32_t saddr, const void* g) {
    asm volatile("cp.async.cg.shared.global [%0], [%1], 16;" :: "r"(saddr), "l"(g));
}
__device__ __forceinline__ void cp_commit() { asm volatile("cp.async.commit_group;"); }
__device__ __forceinline__ void cp_wait1()  { asm volatile("cp.async.wait_group 1;"); }

__device__ __forceinline__ void mma16816(float c[4],
        uint32_t a0, uint32_t a1, uint32_t a2, uint32_t a3,
        uint32_t b0, uint32_t b1) {
    asm volatile("mma.sync.aligned.m16n8k16.row.col.f32.f16.f16.f32 "
        "{%0,%1,%2,%3}, {%4,%5,%6,%7}, {%8,%9}, {%0,%1,%2,%3};"
        : "+f"(c[0]), "+f"(c[1]), "+f"(c[2]), "+f"(c[3])
        : "r"(a0), "r"(a1), "r"(a2), "r"(a3), "r"(b0), "r"(b1));
}
__device__ __forceinline__ void ldsm4(uint32_t* r, uint32_t addr) {
    asm volatile("ldmatrix.sync.aligned.m8n8.x4.shared.b16 {%0,%1,%2,%3}, [%4];"
        : "=r"(r[0]), "=r"(r[1]), "=r"(r[2]), "=r"(r[3]) : "r"(addr));
}
__device__ __forceinline__ void ldsm4t(uint32_t* r, uint32_t addr) {
    asm volatile("ldmatrix.sync.aligned.m8n8.x4.trans.shared.b16 {%0,%1,%2,%3}, [%4];"
        : "=r"(r[0]), "=r"(r[1]), "=r"(r[2]), "=r"(r[3]) : "r"(addr));
}
__device__ __forceinline__ uint32_t packh2(float a, float b) {
    __half2 h = __floats2half2_rn(a, b);
    return *(uint32_t*)&h;
}

// ---------------- merged preprocessing: LoRA weight folding + bias table ----------------
__global__ void fuse_all_kernel(
        const float* __restrict__ W0, const float* __restrict__ la0, const float* __restrict__ lb0, __half* __restrict__ o0,
        const float* __restrict__ W1, const float* __restrict__ la1, const float* __restrict__ lb1, __half* __restrict__ o1,
        const float* __restrict__ W2, const float* __restrict__ la2, const float* __restrict__ lb2, __half* __restrict__ o2,
        const float* __restrict__ W3, const float* __restrict__ la3, const float* __restrict__ lb3, __half* __restrict__ o3,
        const float* __restrict__ rpb) {
    int b = blockIdx.x;
    if (b >= 12288) {
        int u = b - 12288;
        int wl = u >> 4, hh = u & 15;
        int wh = wl >> 2, ww = wl & 3;
        __half* dst = g_biash + ((size_t)(wl * 16 + hh)) * 49 * 52;
        for (int idx = threadIdx.x; idx < 49 * 52; idx += 256) {
            int n = idx / 52, m = idx - (idx / 52) * 52;
            float v = 0.f;
            if (m < 49) {
                int i1 = n / 7, j1 = n - i1 * 7;
                int i2 = m / 7, j2 = m - i2 * 7;
                v = rpb[((i1 - i2 + 6) * 13 + (j1 - j2 + 6)) * NHD + hh];
                int hs1 = wh * 7 + i1, ws1 = ww * 7 + j1;
                int hs2 = wh * 7 + i2, ws2 = ww * 7 + j2;
                int r1 = (hs1 < 21 ? 0 : (hs1 < 25 ? 1 : 2)) * 3 + (ws1 < 21 ? 0 : (ws1 < 25 ? 1 : 2));
                int r2 = (hs2 < 21 ? 0 : (hs2 < 25 ? 1 : 2)) * 3 + (ws2 < 21 ? 0 : (ws2 < 25 ? 1 : 2));
                if (r1 != r2) v -= 100.f;
            }
            dst[idx] = __float2half(v);
        }
        return;
    }
    const float *W, *la, *lb; __half* o; int K, base;
    if (b < 3072)      { W = W0; la = la0; lb = lb0; o = o0; K = CH; base = 0; }
    else if (b < 4096) { W = W1; la = la1; lb = lb1; o = o1; K = CH; base = 3072; }
    else if (b < 8192) { W = W2; la = la2; lb = lb2; o = o2; K = CH; base = 4096; }
    else               { W = W3; la = la3; lb = lb3; o = o3; K = FF; base = 8192; }
    int idx = (b - base) * 256 + threadIdx.x;
    int n = idx / K, k = idx - n * K;
    float acc = W[idx];
#pragma unroll
    for (int r = 0; r < 16; r++) acc += lb[n * 16 + r] * la[(size_t)r * K + k];
    o[idx] = __float2half(acc);
}

// ---------------- layernorm, warp-per-row (no barriers, no smem) ----------------
template <bool GATHER>
__global__ __launch_bounds__(256) void ln_kernel(const float* __restrict__ x,
                          const float* __restrict__ s, const float* __restrict__ b,
                          __half* __restrict__ out) {
    int warp = threadIdx.x >> 5, lane = threadIdx.x & 31;
    int t = blockIdx.x * 8 + warp;
    const float* row;
    if (GATHER) {
        int wnd = t / 49, n = t - wnd * 49;
        int bb = wnd >> 4, wl = wnd & 15;
        int wh = wl >> 2, ww = wl & 3;
        int i = n / 7, j = n - i * 7;
        int h = wh * 7 + i + 3; if (h >= 28) h -= 28;
        int wc = ww * 7 + j + 3; if (wc >= 28) wc -= 28;
        row = x + ((size_t)bb * 784 + h * 28 + wc) * CH;
    } else {
        row = x + (size_t)t * CH;
    }
    float4 v[4];
    float sum = 0.f, sq = 0.f;
#pragma unroll
    for (int i = 0; i < 4; i++) {
        v[i] = ((const float4*)row)[lane + 32 * i];
        sum += v[i].x + v[i].y + v[i].z + v[i].w;
        sq  += v[i].x * v[i].x + v[i].y * v[i].y + v[i].z * v[i].z + v[i].w * v[i].w;
    }
#pragma unroll
    for (int o = 16; o > 0; o >>= 1) {
        sum += __shfl_xor_sync(0xffffffffu, sum, o);
        sq  += __shfl_xor_sync(0xffffffffu, sq, o);
    }
    float mean = sum * (1.f / CH);
    float var  = sq * (1.f / CH) - mean * mean;
    float rstd = rsqrtf(var + 1e-5f);
    __half* orow = out + (size_t)t * CH;
#pragma unroll
    for (int i = 0; i < 4; i++) {
        float4 sv = ((const float4*)s)[lane + 32 * i];
        float4 bv = ((const float4*)b)[lane + 32 * i];
        __half2 h0 = __floats2half2_rn((v[i].x - mean) * rstd * sv.x + bv.x,
                                       (v[i].y - mean) * rstd * sv.y + bv.y);
        __half2 h1 = __floats2half2_rn((v[i].z - mean) * rstd * sv.z + bv.z,
                                       (v[i].w - mean) * rstd * sv.w + bv.w);
        uint2 o2; o2.x = *(uint32_t*)&h0; o2.y = *(uint32_t*)&h1;
        ((uint2*)orow)[lane + 32 * i] = o2;
    }
}

// ---------------- windowed attention: 2 heads/block, trans-V, smem-staged output ----------
__global__ __launch_bounds__(256) void attn_kernel() {
    __shared__ __half Qs[2][64][40];   // rows 49..63 unused garbage (masked by row predicate)
    __shared__ __half Ks[2][56][40];   // rows 49..55 garbage ok (masked by col predicate)
    __shared__ __half Vs[2][64][40];   // natural [m][d]; rows 49..63 zeroed (P*NaN guard)
    __shared__ __half Os[49][72];      // output staging: [n][head_in_pair*32 + d], pad 72
    int w = blockIdx.x, hp = blockIdx.y;
    int tid = threadIdx.x;
    int lane = tid & 31, warp = tid >> 5;
    int h = warp >> 2, lw = warp & 3;
    int gid = lane >> 2, tig = lane & 3;
    int head = hp * 2 + h;
    const __half* Bh = g_biash + ((size_t)((w & 15) * 16 + head)) * 49 * 52;

    // ---- load q/k/v (pure uint4 vector stores) ----
    size_t base = (size_t)w * 49 * C3 + (size_t)hp * 64;
    for (int idx = tid; idx < 49 * 8; idx += 256) {
        int n = idx >> 3, part = idx & 7;
        int hs = part >> 2, dq = (part & 3) * 8;
        size_t off = base + (size_t)n * C3 + hs * 32 + dq;
        *(uint4*)&Qs[hs][n][dq] = *(const uint4*)&g_qkv[off];
        *(uint4*)&Ks[hs][n][dq] = *(const uint4*)&g_qkv[off + 512];
        *(uint4*)&Vs[hs][n][dq] = *(const uint4*)&g_qkv[off + 1024];
    }
    // zero V pad rows 49..63 (contiguous per head: 15*40 halves = 300 uints)
    for (int i = tid; i < 600; i += 256) {
        int a = i / 300, r = i - a * 300;
        ((uint32_t*)&Vs[a][49][0])[r] = 0;
    }
    __syncthreads();

    // ---- S = Q*K^T ----
    float c[7][4];
#pragma unroll
    for (int nt = 0; nt < 7; nt++)
#pragma unroll
        for (int i = 0; i < 4; i++) c[nt][i] = 0.f;
    int r0 = lw * 16 + gid;
    int r1 = r0 + 8;
#pragma unroll
    for (int kk = 0; kk < 2; kk++) {
        int col = kk * 16 + tig * 2;
        uint32_t a0 = *(uint32_t*)&Qs[h][r0][col];
        uint32_t a1 = *(uint32_t*)&Qs[h][r1][col];
        uint32_t a2 = *(uint32_t*)&Qs[h][r0][col + 8];
        uint32_t a3 = *(uint32_t*)&Qs[h][r1][col + 8];
#pragma unroll
        for (int nt = 0; nt < 7; nt++) {
            uint32_t b0 = *(uint32_t*)&Ks[h][nt * 8 + gid][col];
            uint32_t b1 = *(uint32_t*)&Ks[h][nt * 8 + gid][col + 8];
            mma16816(c[nt], a0, a1, a2, a3, b0, b1);
        }
    }

    // ---- scale + bias + mask (fp16 bias table, half2 loads) ----
    const float scale = 0.1767766952966369f;
    bool rv0 = r0 < 49, rv1 = r1 < 49;
#pragma unroll
    for (int nt = 0; nt < 7; nt++) {
        int cc = nt * 8 + 2 * tig;
        float2 b0 = __half22float2(*(const __half2*)&Bh[r0 * 52 + cc]);
        float2 b1 = __half22float2(*(const __half2*)&Bh[r1 * 52 + cc]);
        bool cv0 = cc < 49, cv1 = cc + 1 < 49;
        c[nt][0] = (rv0 && cv0) ? c[nt][0] * scale + b0.x : -1e30f;
        c[nt][1] = (rv0 && cv1) ? c[nt][1] * scale + b0.y : -1e30f;
        c[nt][2] = (rv1 && cv0) ? c[nt][2] * scale + b1.x : -1e30f;
        c[nt][3] = (rv1 && cv1) ? c[nt][3] * scale + b1.y : -1e30f;
    }

    // ---- softmax: quad shuffle reduction ----
    {
        float mx0 = -1e30f, mx1 = -1e30f;
#pragma unroll
        for (int nt = 0; nt < 7; nt++) {
            mx0 = fmaxf(mx0, fmaxf(c[nt][0], c[nt][1]));
            mx1 = fmaxf(mx1, fmaxf(c[nt][2], c[nt][3]));
        }
        mx0 = fmaxf(mx0, __shfl_xor_sync(0xffffffffu, mx0, 1));
        mx0 = fmaxf(mx0, __shfl_xor_sync(0xffffffffu, mx0, 2));
        mx1 = fmaxf(mx1, __shfl_xor_sync(0xffffffffu, mx1, 1));
        mx1 = fmaxf(mx1, __shfl_xor_sync(0xffffffffu, mx1, 2));
        float s0 = 0.f, s1 = 0.f;
#pragma unroll
        for (int nt = 0; nt < 7; nt++) {
            c[nt][0] = __expf(c[nt][0] - mx0); s0 += c[nt][0];
            c[nt][1] = __expf(c[nt][1] - mx0); s0 += c[nt][1];
            c[nt][2] = __expf(c[nt][2] - mx1); s1 += c[nt][2];
            c[nt][3] = __expf(c[nt][3] - mx1); s1 += c[nt][3];
        }
        s0 += __shfl_xor_sync(0xffffffffu, s0, 1);
        s0 += __shfl_xor_sync(0xffffffffu, s0, 2);
        s1 += __shfl_xor_sync(0xffffffffu, s1, 1);
        s1 += __shfl_xor_sync(0xffffffffu, s1, 2);
        float i0 = 1.f / s0, i1 = 1.f / s1;
#pragma unroll
        for (int nt = 0; nt < 7; nt++) {
            c[nt][0] *= i0; c[nt][1] *= i0;
            c[nt][2] *= i1; c[nt][3] *= i1;
        }
    }

    // ---- O = P*V : B fragments via ldmatrix.trans on natural-layout Vs ----
    uint32_t vaddr = (uint32_t)__cvta_generic_to_shared(&Vs[h][0][0])
                   + (uint32_t)(lane & 15) * 80 + (uint32_t)(lane >> 4) * 16;
    float o[4][4];
#pragma unroll
    for (int nt = 0; nt < 4; nt++)
#pragma unroll
        for (int i = 0; i < 4; i++) o[nt][i] = 0.f;
#pragma unroll
    for (int kk = 0; kk < 4; kk++) {
        uint32_t a0, a1, a2, a3;
        if (kk < 3) {
            a0 = packh2(c[2 * kk][0],     c[2 * kk][1]);
            a1 = packh2(c[2 * kk][2],     c[2 * kk][3]);
            a2 = packh2(c[2 * kk + 1][0], c[2 * kk + 1][1]);
            a3 = packh2(c[2 * kk + 1][2], c[2 * kk + 1][3]);
        } else {
            a0 = packh2(c[6][0], c[6][1]);
            a1 = packh2(c[6][2], c[6][3]);
            a2 = 0u; a3 = 0u;
        }
        uint32_t b01[4], b23[4];
        ldsm4t(b01, vaddr + (uint32_t)kk * 1280);        // d 0..15
        ldsm4t(b23, vaddr + (uint32_t)kk * 1280 + 32);   // d 16..31
        mma16816(o[0], a0, a1, a2, a3, b01[0], b01[1]);
        mma16816(o[1], a0, a1, a2, a3, b01[2], b01[3]);
        mma16816(o[2], a0, a1, a2, a3, b23[0], b23[1]);
        mma16816(o[3], a0, a1, a2, a3, b23[2], b23[3]);
    }

    // ---- stage into Os (conflict-free pad), then coalesced store ----
#pragma unroll
    for (int half_ = 0; half_ < 2; half_++) {
        int n = r0 + half_ * 8;
        if (n < 49) {
#pragma unroll
            for (int nt = 0; nt < 4; nt++) {
                int d = h * 32 + nt * 8 + 2 * tig;
                __half2 h2 = __floats2half2_rn(o[nt][half_ * 2 + 0], o[nt][half_ * 2 + 1]);
                *(__half2*)&Os[n][d] = h2;
            }
        }
    }
    __syncthreads();
    for (int idx = tid; idx < 49 * 8; idx += 256) {
        int n = idx >> 3, ch = idx & 7;
        uint4 val = *(const uint4*)&Os[n][ch * 8];
        *(uint4*)&g_attn[((size_t)w * 49 + n) * CH + hp * 64 + ch * 8] = val;
    }
}

// ---------------- fp16 GEMM (R11 winner): 128x128, BK=64, 2-stage .cg, frag dbuf ----------
#define BM 128
#define BN 128
#define BK 64
#define STG_BYTES 16384          // 128*64*2
#define SMEM_GEMM (4 * STG_BYTES)

template <int EPI>
__global__ __launch_bounds__(256, 2)
void gemm_h(const __half* __restrict__ A, const __half* __restrict__ B,
            const float* __restrict__ bias, const float* __restrict__ res,
            void* __restrict__ Cv, int M, int N, int K) {
    extern __shared__ char smem[];
    uint32_t sA0 = (uint32_t)__cvta_generic_to_shared(smem);
    uint32_t sB0 = sA0 + 2 * STG_BYTES;
    int tid = threadIdx.x;
    int lane = tid & 31, warp = tid >> 5;
    int wm = (warp >> 2) * 64, wn = (warp & 3) * 32;
    int bm = blockIdx.y * BM, bn = blockIdx.x * BN;

    float acc[4][4][4];
#pragma unroll
    for (int i = 0; i < 4; i++)
#pragma unroll
        for (int j = 0; j < 4; j++)
#pragma unroll
            for (int k = 0; k < 4; k++) acc[i][j][k] = 0.f;

    int lr = tid >> 2, lc = tid & 3;
    const __half* Ab = A + (size_t)(bm + lr) * K + lc * 8;
    const __half* Bb = B + (size_t)(bn + lr) * K + lc * 8;
    uint32_t stA[4];
    {
        int r1 = lr, r2 = lr + 64;
        stA[0] = r1 * 128 + (((lc)     ^ (r1 & 7)) << 4);
        stA[1] = r1 * 128 + (((lc + 4) ^ (r1 & 7)) << 4);
        stA[2] = r2 * 128 + (((lc)     ^ (r2 & 7)) << 4);
        stA[3] = r2 * 128 + (((lc + 4) ^ (r2 & 7)) << 4);
    }

    uint32_t aOff[4], aXor[4];
#pragma unroll
    for (int mt = 0; mt < 4; mt++) {
        int r = wm + mt * 16 + (lane & 7) + (lane & 8);
        aOff[mt] = r * 128;
        aXor[mt] = (r & 7) << 4;
    }
    int aCs = (lane >> 4) & 1;
    uint32_t bOff[2], bXor[2];
#pragma unroll
    for (int p = 0; p < 2; p++) {
        int r = wn + p * 16 + (lane & 7) + ((lane >> 4) & 1) * 8;
        bOff[p] = r * 128;
        bXor[p] = (r & 7) << 4;
    }
    int bCs = (lane >> 3) & 1;

    int NIT = K / BK;
    {
#pragma unroll
        for (int i = 0; i < 4; i++) {
            cp16(sA0 + stA[i], Ab + ((i >> 1) ? (size_t)64 * K : 0) + ((i & 1) ? 32 : 0));
            cp16(sB0 + stA[i], Bb + ((i >> 1) ? (size_t)64 * K : 0) + ((i & 1) ? 32 : 0));
        }
        cp_commit();
    }
    for (int it = 0; it < NIT; ++it) {
        if (it + 1 < NIT) {
            uint32_t so = ((it + 1) & 1) * STG_BYTES;
            const __half* ap = Ab + (it + 1) * BK;
            const __half* bp = Bb + (it + 1) * BK;
#pragma unroll
            for (int i = 0; i < 4; i++) {
                cp16(sA0 + so + stA[i], ap + ((i >> 1) ? (size_t)64 * K : 0) + ((i & 1) ? 32 : 0));
                cp16(sB0 + so + stA[i], bp + ((i >> 1) ? (size_t)64 * K : 0) + ((i & 1) ? 32 : 0));
            }
        }
        cp_commit();
        cp_wait1();
        __syncthreads();
        uint32_t aBase = sA0 + (it & 1) * STG_BYTES;
        uint32_t bBase = sB0 + (it & 1) * STG_BYTES;

        uint32_t a[2][4][4], b[2][2][4];
        {
            uint32_t cA = ((aCs) << 4);
            uint32_t cB = ((bCs) << 4);
#pragma unroll
            for (int mt = 0; mt < 4; mt++)
                ldsm4(a[0][mt], aBase + aOff[mt] + (cA ^ aXor[mt]));
#pragma unroll
            for (int p = 0; p < 2; p++)
                ldsm4(b[0][p], bBase + bOff[p] + (cB ^ bXor[p]));
        }
#pragma unroll
        for (int kk = 0; kk < 4; kk++) {
            int cur = kk & 1, nxt = cur ^ 1;
            if (kk < 3) {
                uint32_t cA = ((2 * (kk + 1) + aCs) << 4);
                uint32_t cB = ((2 * (kk + 1) + bCs) << 4);
#pragma unroll
                for (int mt = 0; mt < 4; mt++)
                    ldsm4(a[nxt][mt], aBase + aOff[mt] + (cA ^ aXor[mt]));
#pragma unroll
                for (int p = 0; p < 2; p++)
                    ldsm4(b[nxt][p], bBase + bOff[p] + (cB ^ bXor[p]));
            }
#pragma unroll
            for (int mt = 0; mt < 4; mt++)
#pragma unroll
                for (int nt = 0; nt < 4; nt++)
                    mma16816(acc[mt][nt], a[cur][mt][0], a[cur][mt][1],
                             a[cur][mt][2], a[cur][mt][3],
                             b[cur][nt >> 1][(nt & 1) * 2], b[cur][nt >> 1][(nt & 1) * 2 + 1]);
        }
        __syncthreads();
    }

    int gid = lane >> 2, tig = lane & 3;
#pragma unroll
    for (int mt = 0; mt < 4; mt++) {
#pragma unroll
        for (int half_ = 0; half_ < 2; half_++) {
            int m = bm + wm + mt * 16 + gid + half_ * 8;
            size_t drow;
            if (EPI == 2) {
                int wnd = m / 49, n = m - wnd * 49;
                int bb = wnd >> 4, wl = wnd & 15;
                int wh = wl >> 2, ww = wl & 3;
                int ii = n / 7, jj = n - ii * 7;
                int h_ = wh * 7 + ii + 3; if (h_ >= 28) h_ -= 28;
                int w_ = ww * 7 + jj + 3; if (w_ >= 28) w_ -= 28;
                drow = (size_t)(bb * 784 + h_ * 28 + w_);
            } else {
                drow = (size_t)m;
            }
#pragma unroll
            for (int nt = 0; nt < 4; nt++) {
                int cc = bn + wn + nt * 8 + 2 * tig;
                float v0 = acc[mt][nt][half_ * 2 + 0] + bias[cc];
                float v1 = acc[mt][nt][half_ * 2 + 1] + bias[cc + 1];
                if (EPI == 1) { v0 = gelu_exact(v0); v1 = gelu_exact(v1); }
                if (EPI == 2 || EPI == 3) {
                    const float* rrow = res + drow * N;
                    v0 += rrow[cc]; v1 += rrow[cc + 1];
                    float2 o; o.x = v0; o.y = v1;
                    *(float2*)&((float*)Cv)[drow * N + cc] = o;
                } else {
                    __half2 h2 = __floats2half2_rn(v0, v1);
                    *(__half2*)&((__half*)Cv)[drow * N + cc] = h2;
                }
            }
        }
    }
}

// ---------------- launch ----------------
extern "C" void kernel_launch(void* const* d_in, const int* in_sizes, int n_in,
                              void* d_out, int out_size) {
    const float* x      = (const float*)d_in[0];
    const float* ln1_s  = (const float*)d_in[1];
    const float* ln1_b  = (const float*)d_in[2];
    const float* qkv_w  = (const float*)d_in[3];
    const float* qkv_b  = (const float*)d_in[4];
    const float* qkv_la = (const float*)d_in[5];
    const float* qkv_lb = (const float*)d_in[6];
    const float* rpb    = (const float*)d_in[7];
    const float* proj_w = (const float*)d_in[8];
    const float* proj_b = (const float*)d_in[9];
    const float* proj_la= (const float*)d_in[10];
    const float* proj_lb= (const float*)d_in[11];
    const float* ln2_s  = (const float*)d_in[12];
    const float* ln2_b  = (const float*)d_in[13];
    const float* fc1_w  = (const float*)d_in[14];
    const float* fc1_b  = (const float*)d_in[15];
    const float* fc1_la = (const float*)d_in[16];
    const float* fc1_lb = (const float*)d_in[17];
    const float* fc2_w  = (const float*)d_in[18];
    const float* fc2_b  = (const float*)d_in[19];
    const float* fc2_la = (const float*)d_in[20];
    const float* fc2_lb = (const float*)d_in[21];
    float* out = (float*)d_out;

    __half *wqkv, *wproj, *wfc1, *wfc2, *xw, *qkv, *attn, *xn2, *hb;
    float *x2;
    cudaGetSymbolAddress((void**)&wqkv,  g_wqkv);
    cudaGetSymbolAddress((void**)&wproj, g_wproj);
    cudaGetSymbolAddress((void**)&wfc1,  g_wfc1);
    cudaGetSymbolAddress((void**)&wfc2,  g_wfc2);
    cudaGetSymbolAddress((void**)&xw,    g_xw);
    cudaGetSymbolAddress((void**)&qkv,   g_qkv);
    cudaGetSymbolAddress((void**)&attn,  g_attn);
    cudaGetSymbolAddress((void**)&x2,    g_x2);
    cudaGetSymbolAddress((void**)&xn2,   g_xn2);
    cudaGetSymbolAddress((void**)&hb,    g_hbuf);

    cudaFuncSetAttribute(gemm_h<0>, cudaFuncAttributeMaxDynamicSharedMemorySize, SMEM_GEMM);
    cudaFuncSetAttribute(gemm_h<1>, cudaFuncAttributeMaxDynamicSharedMemorySize, SMEM_GEMM);
    cudaFuncSetAttribute(gemm_h<2>, cudaFuncAttributeMaxDynamicSharedMemorySize, SMEM_GEMM);
    cudaFuncSetAttribute(gemm_h<3>, cudaFuncAttributeMaxDynamicSharedMemorySize, SMEM_GEMM);

    // 1) fold LoRA into weights + bias table (one launch)
    fuse_all_kernel<<<12544, 256>>>(qkv_w, qkv_la, qkv_lb, wqkv,
                                    proj_w, proj_la, proj_lb, wproj,
                                    fc1_w, fc1_la, fc1_lb, wfc1,
                                    fc2_w, fc2_la, fc2_lb, wfc2, rpb);

    // 2) LN1 + shift + window partition (warp-per-row)
    ln_kernel<true><<<TOK / 8, 256>>>(x, ln1_s, ln1_b, xw);

    // 3) QKV GEMM
    gemm_h<0><<<dim3(C3 / BN, TOK / BM), 256, SMEM_GEMM>>>(xw, wqkv, qkv_b, nullptr, qkv, TOK, C3, CH);

    // 4) windowed attention (2 heads/block, smem-staged output)
    attn_kernel<<<dim3(NWIN, NHD / 2), 256>>>();

    // 5) proj GEMM + window reverse + reverse shift + residual
    gemm_h<2><<<dim3(CH / BN, TOK / BM), 256, SMEM_GEMM>>>(attn, wproj, proj_b, x, x2, TOK, CH, CH);

    // 6) LN2 (warp-per-row)
    ln_kernel<false><<<TOK / 8, 256>>>(x2, ln2_s, ln2_b, xn2);

    // 7) fc1 + GELU
    gemm_h<1><<<dim3(FF / BN, TOK / BM), 256, SMEM_GEMM>>>(xn2, wfc1, fc1_b, nullptr, hb, TOK, FF, CH);

    // 8) fc2 + residual -> out
    gemm_h<3><<<dim3(CH / BN, TOK / BM), 256, SMEM_GEMM>>>(hb, wfc2, fc2_b, x2, out, TOK, CH, FF);
}

// round 17
// speedup vs baseline: 1.0455x; 1.0146x over previous
#include <cuda_runtime.h>
#include <cuda_fp16.h>
#include <math.h>
#include <stdint.h>

// ---------------- problem constants ----------------
#define TOK   50176
#define CH    512
#define C3    1536
#define FF    2048
#define NHD   16
#define HD    32
#define NWIN  1024

// ---------------- device scratch ----------------
__device__ __half g_wqkv[C3 * CH];            // effective weights, [N][K] K-major
__device__ __half g_wproj[CH * CH];
__device__ __half g_wfc1[FF * CH];
__device__ __half g_wfc2[CH * FF];
__device__ __half g_xw  [(size_t)TOK * CH];
__device__ __half g_qkv [(size_t)TOK * C3];
__device__ __half g_attn[(size_t)TOK * CH];
__device__ __half g_x2  [(size_t)TOK * CH];   // residual 1, natural order (fp16)
__device__ __half g_xn2 [(size_t)TOK * CH];
__device__ __half g_hbuf[(size_t)TOK * FF];
__device__ __half g_biash[16 * 16 * 49 * 52]; // combined rel-pos bias + shift mask (fp16)

// ---------------- helpers ----------------
__device__ __forceinline__ float gelu_exact(float x) {
    return 0.5f * x * (1.0f + erff(x * 0.70710678118654752f));
}
__device__ __forceinline__ void cp16(uint32_t saddr, const void* g) {
    asm volatile("cp.async.cg.shared.global [%0], [%1], 16;" :: "r"(saddr), "l"(g));
}
__device__ __forceinline__ void cp_commit() { asm volatile("cp.async.commit_group;"); }
__device__ __forceinline__ void cp_wait1()  { asm volatile("cp.async.wait_group 1;"); }

__device__ __forceinline__ void mma16816(float c[4],
        uint32_t a0, uint32_t a1, uint32_t a2, uint32_t a3,
        uint32_t b0, uint32_t b1) {
    asm volatile("mma.sync.aligned.m16n8k16.row.col.f32.f16.f16.f32 "
        "{%0,%1,%2,%3}, {%4,%5,%6,%7}, {%8,%9}, {%0,%1,%2,%3};"
        : "+f"(c[0]), "+f"(c[1]), "+f"(c[2]), "+f"(c[3])
        : "r"(a0), "r"(a1), "r"(a2), "r"(a3), "r"(b0), "r"(b1));
}
__device__ __forceinline__ void ldsm4(uint32_t* r, uint32_t addr) {
    asm volatile("ldmatrix.sync.aligned.m8n8.x4.shared.b16 {%0,%1,%2,%3}, [%4];"
        : "=r"(r[0]), "=r"(r[1]), "=r"(r[2]), "=r"(r[3]) : "r"(addr));
}
__device__ __forceinline__ void ldsm4t(uint32_t* r, uint32_t addr) {
    asm volatile("ldmatrix.sync.aligned.m8n8.x4.trans.shared.b16 {%0,%1,%2,%3}, [%4];"
        : "=r"(r[0]), "=r"(r[1]), "=r"(r[2]), "=r"(r[3]) : "r"(addr));
}
__device__ __forceinline__ uint32_t packh2(float a, float b) {
    __half2 h = __floats2half2_rn(a, b);
    return *(uint32_t*)&h;
}

// ---------------- merged preprocessing: LoRA weight folding + bias table ----------------
__global__ void fuse_all_kernel(
        const float* __restrict__ W0, const float* __restrict__ la0, const float* __restrict__ lb0, __half* __restrict__ o0,
        const float* __restrict__ W1, const float* __restrict__ la1, const float* __restrict__ lb1, __half* __restrict__ o1,
        const float* __restrict__ W2, const float* __restrict__ la2, const float* __restrict__ lb2, __half* __restrict__ o2,
        const float* __restrict__ W3, const float* __restrict__ la3, const float* __restrict__ lb3, __half* __restrict__ o3,
        const float* __restrict__ rpb) {
    int b = blockIdx.x;
    if (b >= 12288) {
        int u = b - 12288;
        int wl = u >> 4, hh = u & 15;
        int wh = wl >> 2, ww = wl & 3;
        __half* dst = g_biash + ((size_t)(wl * 16 + hh)) * 49 * 52;
        for (int idx = threadIdx.x; idx < 49 * 52; idx += 256) {
            int n = idx / 52, m = idx - (idx / 52) * 52;
            float v = 0.f;
            if (m < 49) {
                int i1 = n / 7, j1 = n - i1 * 7;
                int i2 = m / 7, j2 = m - i2 * 7;
                v = rpb[((i1 - i2 + 6) * 13 + (j1 - j2 + 6)) * NHD + hh];
                int hs1 = wh * 7 + i1, ws1 = ww * 7 + j1;
                int hs2 = wh * 7 + i2, ws2 = ww * 7 + j2;
                int r1 = (hs1 < 21 ? 0 : (hs1 < 25 ? 1 : 2)) * 3 + (ws1 < 21 ? 0 : (ws1 < 25 ? 1 : 2));
                int r2 = (hs2 < 21 ? 0 : (hs2 < 25 ? 1 : 2)) * 3 + (ws2 < 21 ? 0 : (ws2 < 25 ? 1 : 2));
                if (r1 != r2) v -= 100.f;
            }
            dst[idx] = __float2half(v);
        }
        return;
    }
    const float *W, *la, *lb; __half* o; int K, base;
    if (b < 3072)      { W = W0; la = la0; lb = lb0; o = o0; K = CH; base = 0; }
    else if (b < 4096) { W = W1; la = la1; lb = lb1; o = o1; K = CH; base = 3072; }
    else if (b < 8192) { W = W2; la = la2; lb = lb2; o = o2; K = CH; base = 4096; }
    else               { W = W3; la = la3; lb = lb3; o = o3; K = FF; base = 8192; }
    int idx = (b - base) * 256 + threadIdx.x;
    int n = idx / K, k = idx - n * K;
    float acc = W[idx];
#pragma unroll
    for (int r = 0; r < 16; r++) acc += lb[n * 16 + r] * la[(size_t)r * K + k];
    o[idx] = __float2half(acc);
}

// ---------------- layernorm (fp32 in), warp-per-row ----------------
template <bool GATHER>
__global__ __launch_bounds__(256) void ln_kernel(const float* __restrict__ x,
                          const float* __restrict__ s, const float* __restrict__ b,
                          __half* __restrict__ out) {
    int warp = threadIdx.x >> 5, lane = threadIdx.x & 31;
    int t = blockIdx.x * 8 + warp;
    const float* row;
    if (GATHER) {
        int wnd = t / 49, n = t - wnd * 49;
        int bb = wnd >> 4, wl = wnd & 15;
        int wh = wl >> 2, ww = wl & 3;
        int i = n / 7, j = n - i * 7;
        int h = wh * 7 + i + 3; if (h >= 28) h -= 28;
        int wc = ww * 7 + j + 3; if (wc >= 28) wc -= 28;
        row = x + ((size_t)bb * 784 + h * 28 + wc) * CH;
    } else {
        row = x + (size_t)t * CH;
    }
    float4 v[4];
    float sum = 0.f, sq = 0.f;
#pragma unroll
    for (int i = 0; i < 4; i++) {
        v[i] = ((const float4*)row)[lane + 32 * i];
        sum += v[i].x + v[i].y + v[i].z + v[i].w;
        sq  += v[i].x * v[i].x + v[i].y * v[i].y + v[i].z * v[i].z + v[i].w * v[i].w;
    }
#pragma unroll
    for (int o = 16; o > 0; o >>= 1) {
        sum += __shfl_xor_sync(0xffffffffu, sum, o);
        sq  += __shfl_xor_sync(0xffffffffu, sq, o);
    }
    float mean = sum * (1.f / CH);
    float var  = sq * (1.f / CH) - mean * mean;
    float rstd = rsqrtf(var + 1e-5f);
    __half* orow = out + (size_t)t * CH;
#pragma unroll
    for (int i = 0; i < 4; i++) {
        float4 sv = ((const float4*)s)[lane + 32 * i];
        float4 bv = ((const float4*)b)[lane + 32 * i];
        __half2 h0 = __floats2half2_rn((v[i].x - mean) * rstd * sv.x + bv.x,
                                       (v[i].y - mean) * rstd * sv.y + bv.y);
        __half2 h1 = __floats2half2_rn((v[i].z - mean) * rstd * sv.z + bv.z,
                                       (v[i].w - mean) * rstd * sv.w + bv.w);
        uint2 o2; o2.x = *(uint32_t*)&h0; o2.y = *(uint32_t*)&h1;
        ((uint2*)orow)[lane + 32 * i] = o2;
    }
}

// ---------------- layernorm (fp16 in), warp-per-row ----------------
__global__ __launch_bounds__(256) void ln2h_kernel(const __half* __restrict__ x,
                          const float* __restrict__ s, const float* __restrict__ b,
                          __half* __restrict__ out) {
    int warp = threadIdx.x >> 5, lane = threadIdx.x & 31;
    int t = blockIdx.x * 8 + warp;
    const __half* row = x + (size_t)t * CH;
    float vv[16];
    float sum = 0.f, sq = 0.f;
#pragma unroll
    for (int i = 0; i < 4; i++) {
        uint2 u = ((const uint2*)row)[lane + 32 * i];
        float2 f0 = __half22float2(*(__half2*)&u.x);
        float2 f1 = __half22float2(*(__half2*)&u.y);
        vv[i * 4 + 0] = f0.x; vv[i * 4 + 1] = f0.y;
        vv[i * 4 + 2] = f1.x; vv[i * 4 + 3] = f1.y;
        sum += f0.x + f0.y + f1.x + f1.y;
        sq  += f0.x * f0.x + f0.y * f0.y + f1.x * f1.x + f1.y * f1.y;
    }
#pragma unroll
    for (int o = 16; o > 0; o >>= 1) {
        sum += __shfl_xor_sync(0xffffffffu, sum, o);
        sq  += __shfl_xor_sync(0xffffffffu, sq, o);
    }
    float mean = sum * (1.f / CH);
    float var  = sq * (1.f / CH) - mean * mean;
    float rstd = rsqrtf(var + 1e-5f);
    __half* orow = out + (size_t)t * CH;
#pragma unroll
    for (int i = 0; i < 4; i++) {
        float4 sv = ((const float4*)s)[lane + 32 * i];
        float4 bv = ((const float4*)b)[lane + 32 * i];
        __half2 h0 = __floats2half2_rn((vv[i*4+0] - mean) * rstd * sv.x + bv.x,
                                       (vv[i*4+1] - mean) * rstd * sv.y + bv.y);
        __half2 h1 = __floats2half2_rn((vv[i*4+2] - mean) * rstd * sv.z + bv.z,
                                       (vv[i*4+3] - mean) * rstd * sv.w + bv.w);
        uint2 o2; o2.x = *(uint32_t*)&h0; o2.y = *(uint32_t*)&h1;
        ((uint2*)orow)[lane + 32 * i] = o2;
    }
}

// ---------------- windowed attention: 2 heads/block, trans-V, smem-staged output ----------
__global__ __launch_bounds__(256) void attn_kernel() {
    __shared__ __half Qs[2][64][40];
    __shared__ __half Ks[2][56][40];
    __shared__ __half Vs[2][64][40];   // rows 49..63 zeroed (P*NaN guard)
    __shared__ __half Os[49][72];
    int w = blockIdx.x, hp = blockIdx.y;
    int tid = threadIdx.x;
    int lane = tid & 31, warp = tid >> 5;
    int h = warp >> 2, lw = warp & 3;
    int gid = lane >> 2, tig = lane & 3;
    int head = hp * 2 + h;
    const __half* Bh = g_biash + ((size_t)((w & 15) * 16 + head)) * 49 * 52;

    size_t base = (size_t)w * 49 * C3 + (size_t)hp * 64;
    for (int idx = tid; idx < 49 * 8; idx += 256) {
        int n = idx >> 3, part = idx & 7;
        int hs = part >> 2, dq = (part & 3) * 8;
        size_t off = base + (size_t)n * C3 + hs * 32 + dq;
        *(uint4*)&Qs[hs][n][dq] = *(const uint4*)&g_qkv[off];
        *(uint4*)&Ks[hs][n][dq] = *(const uint4*)&g_qkv[off + 512];
        *(uint4*)&Vs[hs][n][dq] = *(const uint4*)&g_qkv[off + 1024];
    }
    for (int i = tid; i < 600; i += 256) {
        int a = i / 300, r = i - a * 300;
        ((uint32_t*)&Vs[a][49][0])[r] = 0;
    }
    __syncthreads();

    float c[7][4];
#pragma unroll
    for (int nt = 0; nt < 7; nt++)
#pragma unroll
        for (int i = 0; i < 4; i++) c[nt][i] = 0.f;
    int r0 = lw * 16 + gid;
    int r1 = r0 + 8;
#pragma unroll
    for (int kk = 0; kk < 2; kk++) {
        int col = kk * 16 + tig * 2;
        uint32_t a0 = *(uint32_t*)&Qs[h][r0][col];
        uint32_t a1 = *(uint32_t*)&Qs[h][r1][col];
        uint32_t a2 = *(uint32_t*)&Qs[h][r0][col + 8];
        uint32_t a3 = *(uint32_t*)&Qs[h][r1][col + 8];
#pragma unroll
        for (int nt = 0; nt < 7; nt++) {
            uint32_t b0 = *(uint32_t*)&Ks[h][nt * 8 + gid][col];
            uint32_t b1 = *(uint32_t*)&Ks[h][nt * 8 + gid][col + 8];
            mma16816(c[nt], a0, a1, a2, a3, b0, b1);
        }
    }

    const float scale = 0.1767766952966369f;
    bool rv0 = r0 < 49, rv1 = r1 < 49;
#pragma unroll
    for (int nt = 0; nt < 7; nt++) {
        int cc = nt * 8 + 2 * tig;
        float2 b0 = __half22float2(*(const __half2*)&Bh[r0 * 52 + cc]);
        float2 b1 = __half22float2(*(const __half2*)&Bh[r1 * 52 + cc]);
        bool cv0 = cc < 49, cv1 = cc + 1 < 49;
        c[nt][0] = (rv0 && cv0) ? c[nt][0] * scale + b0.x : -1e30f;
        c[nt][1] = (rv0 && cv1) ? c[nt][1] * scale + b0.y : -1e30f;
        c[nt][2] = (rv1 && cv0) ? c[nt][2] * scale + b1.x : -1e30f;
        c[nt][3] = (rv1 && cv1) ? c[nt][3] * scale + b1.y : -1e30f;
    }

    {
        float mx0 = -1e30f, mx1 = -1e30f;
#pragma unroll
        for (int nt = 0; nt < 7; nt++) {
            mx0 = fmaxf(mx0, fmaxf(c[nt][0], c[nt][1]));
            mx1 = fmaxf(mx1, fmaxf(c[nt][2], c[nt][3]));
        }
        mx0 = fmaxf(mx0, __shfl_xor_sync(0xffffffffu, mx0, 1));
        mx0 = fmaxf(mx0, __shfl_xor_sync(0xffffffffu, mx0, 2));
        mx1 = fmaxf(mx1, __shfl_xor_sync(0xffffffffu, mx1, 1));
        mx1 = fmaxf(mx1, __shfl_xor_sync(0xffffffffu, mx1, 2));
        float s0 = 0.f, s1 = 0.f;
#pragma unroll
        for (int nt = 0; nt < 7; nt++) {
            c[nt][0] = __expf(c[nt][0] - mx0); s0 += c[nt][0];
            c[nt][1] = __expf(c[nt][1] - mx0); s0 += c[nt][1];
            c[nt][2] = __expf(c[nt][2] - mx1); s1 += c[nt][2];
            c[nt][3] = __expf(c[nt][3] - mx1); s1 += c[nt][3];
        }
        s0 += __shfl_xor_sync(0xffffffffu, s0, 1);
        s0 += __shfl_xor_sync(0xffffffffu, s0, 2);
        s1 += __shfl_xor_sync(0xffffffffu, s1, 1);
        s1 += __shfl_xor_sync(0xffffffffu, s1, 2);
        float i0 = 1.f / s0, i1 = 1.f / s1;
#pragma unroll
        for (int nt = 0; nt < 7; nt++) {
            c[nt][0] *= i0; c[nt][1] *= i0;
            c[nt][2] *= i1; c[nt][3] *= i1;
        }
    }

    uint32_t vaddr = (uint32_t)__cvta_generic_to_shared(&Vs[h][0][0])
                   + (uint32_t)(lane & 15) * 80 + (uint32_t)(lane >> 4) * 16;
    float o[4][4];
#pragma unroll
    for (int nt = 0; nt < 4; nt++)
#pragma unroll
        for (int i = 0; i < 4; i++) o[nt][i] = 0.f;
#pragma unroll
    for (int kk = 0; kk < 4; kk++) {
        uint32_t a0, a1, a2, a3;
        if (kk < 3) {
            a0 = packh2(c[2 * kk][0],     c[2 * kk][1]);
            a1 = packh2(c[2 * kk][2],     c[2 * kk][3]);
            a2 = packh2(c[2 * kk + 1][0], c[2 * kk + 1][1]);
            a3 = packh2(c[2 * kk + 1][2], c[2 * kk + 1][3]);
        } else {
            a0 = packh2(c[6][0], c[6][1]);
            a1 = packh2(c[6][2], c[6][3]);
            a2 = 0u; a3 = 0u;
        }
        uint32_t b01[4], b23[4];
        ldsm4t(b01, vaddr + (uint32_t)kk * 1280);
        ldsm4t(b23, vaddr + (uint32_t)kk * 1280 + 32);
        mma16816(o[0], a0, a1, a2, a3, b01[0], b01[1]);
        mma16816(o[1], a0, a1, a2, a3, b01[2], b01[3]);
        mma16816(o[2], a0, a1, a2, a3, b23[0], b23[1]);
        mma16816(o[3], a0, a1, a2, a3, b23[2], b23[3]);
    }

#pragma unroll
    for (int half_ = 0; half_ < 2; half_++) {
        int n = r0 + half_ * 8;
        if (n < 49) {
#pragma unroll
            for (int nt = 0; nt < 4; nt++) {
                int d = h * 32 + nt * 8 + 2 * tig;
                __half2 h2 = __floats2half2_rn(o[nt][half_ * 2 + 0], o[nt][half_ * 2 + 1]);
                *(__half2*)&Os[n][d] = h2;
            }
        }
    }
    __syncthreads();
    for (int idx = tid; idx < 49 * 8; idx += 256) {
        int n = idx >> 3, ch = idx & 7;
        uint4 val = *(const uint4*)&Os[n][ch * 8];
        *(uint4*)&g_attn[((size_t)w * 49 + n) * CH + hp * 64 + ch * 8] = val;
    }
}

// ---------------- fp16 GEMM (R11 winner): 128x128, BK=64, 2-stage .cg, frag dbuf ----------
// EPI: 0 bias (half out), 1 bias+GELU (half out),
//      2 proj scatter + fp32 residual -> HALF out, 3 bias + half residual -> f32 out
#define BM 128
#define BN 128
#define BK 64
#define STG_BYTES 16384          // 128*64*2
#define SMEM_GEMM (4 * STG_BYTES)

template <int EPI>
__global__ __launch_bounds__(256, 2)
void gemm_h(const __half* __restrict__ A, const __half* __restrict__ B,
            const float* __restrict__ bias, const void* __restrict__ res,
            void* __restrict__ Cv, int M, int N, int K) {
    extern __shared__ char smem[];
    uint32_t sA0 = (uint32_t)__cvta_generic_to_shared(smem);
    uint32_t sB0 = sA0 + 2 * STG_BYTES;
    int tid = threadIdx.x;
    int lane = tid & 31, warp = tid >> 5;
    int wm = (warp >> 2) * 64, wn = (warp & 3) * 32;
    int bm = blockIdx.y * BM, bn = blockIdx.x * BN;

    float acc[4][4][4];
#pragma unroll
    for (int i = 0; i < 4; i++)
#pragma unroll
        for (int j = 0; j < 4; j++)
#pragma unroll
            for (int k = 0; k < 4; k++) acc[i][j][k] = 0.f;

    int lr = tid >> 2, lc = tid & 3;
    const __half* Ab = A + (size_t)(bm + lr) * K + lc * 8;
    const __half* Bb = B + (size_t)(bn + lr) * K + lc * 8;
    uint32_t stA[4];
    {
        int r1 = lr, r2 = lr + 64;
        stA[0] = r1 * 128 + (((lc)     ^ (r1 & 7)) << 4);
        stA[1] = r1 * 128 + (((lc + 4) ^ (r1 & 7)) << 4);
        stA[2] = r2 * 128 + (((lc)     ^ (r2 & 7)) << 4);
        stA[3] = r2 * 128 + (((lc + 4) ^ (r2 & 7)) << 4);
    }

    uint32_t aOff[4], aXor[4];
#pragma unroll
    for (int mt = 0; mt < 4; mt++) {
        int r = wm + mt * 16 + (lane & 7) + (lane & 8);
        aOff[mt] = r * 128;
        aXor[mt] = (r & 7) << 4;
    }
    int aCs = (lane >> 4) & 1;
    uint32_t bOff[2], bXor[2];
#pragma unroll
    for (int p = 0; p < 2; p++) {
        int r = wn + p * 16 + (lane & 7) + ((lane >> 4) & 1) * 8;
        bOff[p] = r * 128;
        bXor[p] = (r & 7) << 4;
    }
    int bCs = (lane >> 3) & 1;

    int NIT = K / BK;
    {
#pragma unroll
        for (int i = 0; i < 4; i++) {
            cp16(sA0 + stA[i], Ab + ((i >> 1) ? (size_t)64 * K : 0) + ((i & 1) ? 32 : 0));
            cp16(sB0 + stA[i], Bb + ((i >> 1) ? (size_t)64 * K : 0) + ((i & 1) ? 32 : 0));
        }
        cp_commit();
    }
    for (int it = 0; it < NIT; ++it) {
        if (it + 1 < NIT) {
            uint32_t so = ((it + 1) & 1) * STG_BYTES;
            const __half* ap = Ab + (it + 1) * BK;
            const __half* bp = Bb + (it + 1) * BK;
#pragma unroll
            for (int i = 0; i < 4; i++) {
                cp16(sA0 + so + stA[i], ap + ((i >> 1) ? (size_t)64 * K : 0) + ((i & 1) ? 32 : 0));
                cp16(sB0 + so + stA[i], bp + ((i >> 1) ? (size_t)64 * K : 0) + ((i & 1) ? 32 : 0));
            }
        }
        cp_commit();
        cp_wait1();
        __syncthreads();
        uint32_t aBase = sA0 + (it & 1) * STG_BYTES;
        uint32_t bBase = sB0 + (it & 1) * STG_BYTES;

        uint32_t a[2][4][4], b[2][2][4];
        {
            uint32_t cA = ((aCs) << 4);
            uint32_t cB = ((bCs) << 4);
#pragma unroll
            for (int mt = 0; mt < 4; mt++)
                ldsm4(a[0][mt], aBase + aOff[mt] + (cA ^ aXor[mt]));
#pragma unroll
            for (int p = 0; p < 2; p++)
                ldsm4(b[0][p], bBase + bOff[p] + (cB ^ bXor[p]));
        }
#pragma unroll
        for (int kk = 0; kk < 4; kk++) {
            int cur = kk & 1, nxt = cur ^ 1;
            if (kk < 3) {
                uint32_t cA = ((2 * (kk + 1) + aCs) << 4);
                uint32_t cB = ((2 * (kk + 1) + bCs) << 4);
#pragma unroll
                for (int mt = 0; mt < 4; mt++)
                    ldsm4(a[nxt][mt], aBase + aOff[mt] + (cA ^ aXor[mt]));
#pragma unroll
                for (int p = 0; p < 2; p++)
                    ldsm4(b[nxt][p], bBase + bOff[p] + (cB ^ bXor[p]));
            }
#pragma unroll
            for (int mt = 0; mt < 4; mt++)
#pragma unroll
                for (int nt = 0; nt < 4; nt++)
                    mma16816(acc[mt][nt], a[cur][mt][0], a[cur][mt][1],
                             a[cur][mt][2], a[cur][mt][3],
                             b[cur][nt >> 1][(nt & 1) * 2], b[cur][nt >> 1][(nt & 1) * 2 + 1]);
        }
        __syncthreads();
    }

    int gid = lane >> 2, tig = lane & 3;
#pragma unroll
    for (int mt = 0; mt < 4; mt++) {
#pragma unroll
        for (int half_ = 0; half_ < 2; half_++) {
            int m = bm + wm + mt * 16 + gid + half_ * 8;
            size_t drow;
            if (EPI == 2) {
                int wnd = m / 49, n = m - wnd * 49;
                int bb = wnd >> 4, wl = wnd & 15;
                int wh = wl >> 2, ww = wl & 3;
                int ii = n / 7, jj = n - ii * 7;
                int h_ = wh * 7 + ii + 3; if (h_ >= 28) h_ -= 28;
                int w_ = ww * 7 + jj + 3; if (w_ >= 28) w_ -= 28;
                drow = (size_t)(bb * 784 + h_ * 28 + w_);
            } else {
                drow = (size_t)m;
            }
#pragma unroll
            for (int nt = 0; nt < 4; nt++) {
                int cc = bn + wn + nt * 8 + 2 * tig;
                float v0 = acc[mt][nt][half_ * 2 + 0] + bias[cc];
                float v1 = acc[mt][nt][half_ * 2 + 1] + bias[cc + 1];
                if (EPI == 1) { v0 = gelu_exact(v0); v1 = gelu_exact(v1); }
                if (EPI == 2) {
                    // fp32 residual (original x), half output (x2)
                    const float* rrow = (const float*)res + drow * N;
                    v0 += rrow[cc]; v1 += rrow[cc + 1];
                    __half2 h2 = __floats2half2_rn(v0, v1);
                    *(__half2*)&((__half*)Cv)[drow * N + cc] = h2;
                } else if (EPI == 3) {
                    // half residual (x2), fp32 output (final)
                    const __half* rrow = (const __half*)res + drow * N;
                    float2 r2 = __half22float2(*(const __half2*)&rrow[cc]);
                    v0 += r2.x; v1 += r2.y;
                    float2 o; o.x = v0; o.y = v1;
                    *(float2*)&((float*)Cv)[drow * N + cc] = o;
                } else {
                    __half2 h2 = __floats2half2_rn(v0, v1);
                    *(__half2*)&((__half*)Cv)[drow * N + cc] = h2;
                }
            }
        }
    }
}

// ---------------- launch ----------------
extern "C" void kernel_launch(void* const* d_in, const int* in_sizes, int n_in,
                              void* d_out, int out_size) {
    const float* x      = (const float*)d_in[0];
    const float* ln1_s  = (const float*)d_in[1];
    const float* ln1_b  = (const float*)d_in[2];
    const float* qkv_w  = (const float*)d_in[3];
    const float* qkv_b  = (const float*)d_in[4];
    const float* qkv_la = (const float*)d_in[5];
    const float* qkv_lb = (const float*)d_in[6];
    const float* rpb    = (const float*)d_in[7];
    const float* proj_w = (const float*)d_in[8];
    const float* proj_b = (const float*)d_in[9];
    const float* proj_la= (const float*)d_in[10];
    const float* proj_lb= (const float*)d_in[11];
    const float* ln2_s  = (const float*)d_in[12];
    const float* ln2_b  = (const float*)d_in[13];
    const float* fc1_w  = (const float*)d_in[14];
    const float* fc1_b  = (const float*)d_in[15];
    const float* fc1_la = (const float*)d_in[16];
    const float* fc1_lb = (const float*)d_in[17];
    const float* fc2_w  = (const float*)d_in[18];
    const float* fc2_b  = (const float*)d_in[19];
    const float* fc2_la = (const float*)d_in[20];
    const float* fc2_lb = (const float*)d_in[21];
    float* out = (float*)d_out;

    __half *wqkv, *wproj, *wfc1, *wfc2, *xw, *qkv, *attn, *x2, *xn2, *hb;
    cudaGetSymbolAddress((void**)&wqkv,  g_wqkv);
    cudaGetSymbolAddress((void**)&wproj, g_wproj);
    cudaGetSymbolAddress((void**)&wfc1,  g_wfc1);
    cudaGetSymbolAddress((void**)&wfc2,  g_wfc2);
    cudaGetSymbolAddress((void**)&xw,    g_xw);
    cudaGetSymbolAddress((void**)&qkv,   g_qkv);
    cudaGetSymbolAddress((void**)&attn,  g_attn);
    cudaGetSymbolAddress((void**)&x2,    g_x2);
    cudaGetSymbolAddress((void**)&xn2,   g_xn2);
    cudaGetSymbolAddress((void**)&hb,    g_hbuf);

    cudaFuncSetAttribute(gemm_h<0>, cudaFuncAttributeMaxDynamicSharedMemorySize, SMEM_GEMM);
    cudaFuncSetAttribute(gemm_h<1>, cudaFuncAttributeMaxDynamicSharedMemorySize, SMEM_GEMM);
    cudaFuncSetAttribute(gemm_h<2>, cudaFuncAttributeMaxDynamicSharedMemorySize, SMEM_GEMM);
    cudaFuncSetAttribute(gemm_h<3>, cudaFuncAttributeMaxDynamicSharedMemorySize, SMEM_GEMM);

    // 1) fold LoRA into weights + bias table (one launch)
    fuse_all_kernel<<<12544, 256>>>(qkv_w, qkv_la, qkv_lb, wqkv,
                                    proj_w, proj_la, proj_lb, wproj,
                                    fc1_w, fc1_la, fc1_lb, wfc1,
                                    fc2_w, fc2_la, fc2_lb, wfc2, rpb);

    // 2) LN1 + shift + window partition (warp-per-row)
    ln_kernel<true><<<TOK / 8, 256>>>(x, ln1_s, ln1_b, xw);

    // 3) QKV GEMM
    gemm_h<0><<<dim3(C3 / BN, TOK / BM), 256, SMEM_GEMM>>>(xw, wqkv, qkv_b, nullptr, qkv, TOK, C3, CH);

    // 4) windowed attention (2 heads/block, smem-staged output)
    attn_kernel<<<dim3(NWIN, NHD / 2), 256>>>();

    // 5) proj GEMM + window reverse + reverse shift + fp32 residual -> half x2
    gemm_h<2><<<dim3(CH / BN, TOK / BM), 256, SMEM_GEMM>>>(attn, wproj, proj_b, x, x2, TOK, CH, CH);

    // 6) LN2 (half in, warp-per-row)
    ln2h_kernel<<<TOK / 8, 256>>>(x2, ln2_s, ln2_b, xn2);

    // 7) fc1 + GELU
    gemm_h<1><<<dim3(FF / BN, TOK / BM), 256, SMEM_GEMM>>>(xn2, wfc1, fc1_b, nullptr, hb, TOK, FF, CH);

    // 8) fc2 + half residual -> fp32 out
    gemm_h<3><<<dim3(CH / BN, TOK / BM), 256, SMEM_GEMM>>>(hb, wfc2, fc2_b, x2, out, TOK, CH, FF);
}